// round 9
// baseline (speedup 1.0000x reference)
#include <cuda_runtime.h>
#include <cuda_bf16.h>
#include <cuda_fp16.h>
#include <math.h>
#include <stdint.h>

// Problem constants
#define Bv   8
#define Sv   2048
#define Dv   1024
#define Hv   16
#define HDv  64
#define HIDv 256
#define BHv  128               // B*H
#define Mv   (Bv*Sv)           // 16384 rows of x
#define MTv  (BHv*Sv)          // 262144 rows per-head

typedef __nv_bfloat16 bf16;
typedef __half f16;

// ------------------------- scratch (device globals) -------------------------
__device__ f16  g_xnh[Mv*Dv];         // 32 MB  (normed x, fp16; store then retrieve)
__device__ f16  g_wkv[2*Dv*Dv];       // 4 MB   (W_K^T | W_V^T fp16, [2048][1024])
__device__ f16  g_wqhi[Dv*Dv];        // 2 MB
__device__ f16  g_wqlo[Dv*Dv];        // 2 MB
__device__ float g_values[MTv*HDv];   // 64 MB
__device__ float g_q[MTv*HDv];        // 64 MB (normed q, fp32)
__device__ float g_pre1[MTv*HDv];     // 64 MB
__device__ f16  g_keysb[MTv*HDv];     // 32 MB (normed keys, fp16)
__device__ bf16 g_qhi[MTv*HDv];       // 32 MB
__device__ bf16 g_qlo[MTv*HDv];       // 32 MB
__device__ f16  g_dhb[MTv*HDv];       // 32 MB
// pooled scratch: pre0h@0, h1h@128M, dh0h@256M; retrieve: h1rhi@0, h1rlo@256M
__device__ __align__(256) char g_pool[402653184];   // 384 MB
__device__ float g_alpha[BHv*Sv];
__device__ float g_theta[BHv*Sv];
__device__ float g_amean[BHv];
__device__ float g_coef[BHv];
__device__ float g_g0[BHv*HIDv*HDv];  // g0^T [bh][256][64] fp32
__device__ float g_g1[BHv*HDv*HIDv];  // g1^T [bh][64][256] fp32
__device__ float g_mW0T[HIDv*HDv];    __device__ f16 g_mW0Tb[HIDv*HDv];
__device__ float g_mW1T[HDv*HIDv];    __device__ f16 g_mW1Tb[HDv*HIDv];
__device__ f16 g_mW1b[HIDv*HDv];
__device__ bf16 g_nW0Thi[BHv*HIDv*HDv], g_nW0Tlo[BHv*HIDv*HDv];
__device__ bf16 g_nW1Thi[BHv*HDv*HIDv], g_nW1Tlo[BHv*HDv*HIDv];

// ========================= mma.sync helpers =================================
__device__ __forceinline__ uint32_t smem_u32(const void* p) {
    uint32_t a;
    asm("{ .reg .u64 t; cvta.to.shared.u64 t, %1; cvt.u32.u64 %0, t; }"
        : "=r"(a) : "l"(p));
    return a;
}
__device__ __forceinline__ void ldsm4(uint32_t* d, uint32_t addr) {
    asm volatile("ldmatrix.sync.aligned.m8n8.x4.shared.b16 {%0,%1,%2,%3}, [%4];"
                 : "=r"(d[0]), "=r"(d[1]), "=r"(d[2]), "=r"(d[3]) : "r"(addr));
}
__device__ __forceinline__ void ldsm4t(uint32_t* d, uint32_t addr) {
    asm volatile("ldmatrix.sync.aligned.m8n8.x4.trans.shared.b16 {%0,%1,%2,%3}, [%4];"
                 : "=r"(d[0]), "=r"(d[1]), "=r"(d[2]), "=r"(d[3]) : "r"(addr));
}
template <typename T> struct MmaOp;
template <> struct MmaOp<bf16> {
    static __device__ __forceinline__ void run(float* c, const uint32_t* a, const uint32_t* b) {
        asm volatile("mma.sync.aligned.m16n8k16.row.col.f32.bf16.bf16.f32 "
                     "{%0,%1,%2,%3}, {%4,%5,%6,%7}, {%8,%9}, {%0,%1,%2,%3};"
                     : "+f"(c[0]), "+f"(c[1]), "+f"(c[2]), "+f"(c[3])
                     : "r"(a[0]), "r"(a[1]), "r"(a[2]), "r"(a[3]), "r"(b[0]), "r"(b[1]));
    }
};
template <> struct MmaOp<f16> {
    static __device__ __forceinline__ void run(float* c, const uint32_t* a, const uint32_t* b) {
        asm volatile("mma.sync.aligned.m16n8k16.row.col.f32.f16.f16.f32 "
                     "{%0,%1,%2,%3}, {%4,%5,%6,%7}, {%8,%9}, {%0,%1,%2,%3};"
                     : "+f"(c[0]), "+f"(c[1]), "+f"(c[2]), "+f"(c[3])
                     : "r"(a[0]), "r"(a[1]), "r"(a[2]), "r"(a[3]), "r"(b[0]), "r"(b[1]));
    }
};
template <typename T> __device__ __forceinline__ T fromf(float v);
template <> __device__ __forceinline__ bf16 fromf<bf16>(float v) { return __float2bfloat16(v); }
template <> __device__ __forceinline__ f16  fromf<f16>(float v)  { return __float2half(v); }
__device__ __forceinline__ float tof(bf16 v) { return __bfloat162float(v); }
__device__ __forceinline__ float tof(f16 v)  { return __half2float(v); }

__device__ __forceinline__ void cp16(uint32_t dst, const void* src) {
    asm volatile("cp.async.cg.shared.global [%0], [%1], 16;" :: "r"(dst), "l"(src) : "memory");
}
__device__ __forceinline__ float geluf(float v) {
    return 0.5f * v * (1.f + erff(v * 0.70710678118654752f));
}
__device__ __forceinline__ float gelugrad(float p) {
    float cdf = 0.5f * (1.f + erff(p * 0.70710678118654752f));
    float pdf = expf(-0.5f * p * p) * 0.3989422804014327f;
    return cdf + p * pdf;
}

// ---------------- rmsnorm over D=1024 rows, emit fp16 -----------------------
__global__ void k_rmsnorm16(const float* __restrict__ x, const float* __restrict__ w,
                            f16* __restrict__ o) {
    int row = blockIdx.x;
    const float* xr = x + (size_t)row * Dv;
    int tid = threadIdx.x;  // 256
    float v[4]; float ss = 0.f;
#pragma unroll
    for (int i = 0; i < 4; i++) { v[i] = xr[tid + i*256]; ss += v[i]*v[i]; }
#pragma unroll
    for (int o2 = 16; o2 > 0; o2 >>= 1) ss += __shfl_xor_sync(0xffffffffu, ss, o2);
    __shared__ float red[8];
    __shared__ float rinv;
    if ((tid & 31) == 0) red[tid >> 5] = ss;
    __syncthreads();
    if (tid == 0) {
        float t = 0.f;
#pragma unroll
        for (int i = 0; i < 8; i++) t += red[i];
        rinv = rsqrtf(t / (float)Dv + 1e-6f);
    }
    __syncthreads();
    float r = rinv;
#pragma unroll
    for (int i = 0; i < 4; i++)
        o[(size_t)row*Dv + tid + i*256] = __float2half(v[i] * w[tid + i*256] * r);
}

// ---------------- transpose weight -> fp16 (single) -------------------------
__global__ void k_wt16(const float* __restrict__ W, f16* __restrict__ T) {
    __shared__ float t[32][33];
    int k0 = blockIdx.y * 32, n0 = blockIdx.x * 32;
    int tx = threadIdx.x, ty = threadIdx.y;   // (32, 8)
#pragma unroll
    for (int r = 0; r < 4; r++)
        t[ty + r*8][tx] = W[(size_t)(k0 + ty + r*8)*Dv + n0 + tx];
    __syncthreads();
#pragma unroll
    for (int r = 0; r < 4; r++)
        T[(size_t)(n0 + ty + r*8)*Dv + k0 + tx] = __float2half(t[tx][ty + r*8]);
}

// ---------------- transpose weight -> fp16 hi/lo -----------------------------
__global__ void k_wt2(const float* __restrict__ W,
                      f16* __restrict__ Thi, f16* __restrict__ Tlo) {
    __shared__ float t[32][33];
    int k0 = blockIdx.y * 32, n0 = blockIdx.x * 32;
    int tx = threadIdx.x, ty = threadIdx.y;
#pragma unroll
    for (int r = 0; r < 4; r++)
        t[ty + r*8][tx] = W[(size_t)(k0 + ty + r*8)*Dv + n0 + tx];
    __syncthreads();
#pragma unroll
    for (int r = 0; r < 4; r++) {
        float v = t[tx][ty + r*8];
        f16 h = __float2half(v);
        size_t off = (size_t)(n0 + ty + r*8)*Dv + k0 + tx;
        Thi[off] = h;
        Tlo[off] = __float2half(v - __half2float(h));
    }
}

// ===== fused K+V GEMM: (16384x1024)@(1024x2048) fp16 single-pass ============
// cols [0,1024): K proj -> fused head-rmsnorm(knw) -> keysb fp16
// cols [1024,2048): V proj -> raw fp32 values
#define KV_SMEM (2*32768)
__global__ void __launch_bounds__(256)
k_gemm_kv(const f16* __restrict__ A, const f16* __restrict__ Bw,
          f16* __restrict__ keysb, float* __restrict__ values,
          const float* __restrict__ knw) {
    extern __shared__ char smem[];
    uint32_t sb = smem_u32(smem);
    int tid = threadIdx.x;
    int wid = tid >> 5, lane = tid & 31;
    int wm = wid >> 1, wn = wid & 1;          // 4(M) x 2(N)
    int m0 = blockIdx.y * 128, n0 = blockIdx.x * 128;

#define LOAD_KV(CH, ST) do {                                                   \
    int _k0 = (CH) * 64;                                                       \
    uint32_t _sb = sb + (ST) * 32768;                                          \
    _Pragma("unroll")                                                          \
    for (int i = 0; i < 8; i++) {                                              \
        int idx = i * 256 + tid;                                               \
        int layer = idx >> 10, rem = idx & 1023;                               \
        int r = rem >> 3, g = rem & 7;                                         \
        const f16* src = layer ? Bw + (size_t)(n0 + r) * Dv + _k0 + g * 8      \
                               : A  + (size_t)(m0 + r) * Dv + _k0 + g * 8;     \
        cp16(_sb + layer * 16384 + r * 128 + ((g ^ (r & 7)) << 4), src);       \
    }                                                                          \
    asm volatile("cp.async.commit_group;" ::: "memory");                       \
} while (0)

    LOAD_KV(0, 0);
    float acc[2][8][4];
#pragma unroll
    for (int mt = 0; mt < 2; mt++)
#pragma unroll
        for (int nt = 0; nt < 8; nt++)
#pragma unroll
            for (int e = 0; e < 4; e++) acc[mt][nt][e] = 0.f;

    for (int ch = 0; ch < 16; ch++) {
        if (ch < 15) {
            LOAD_KV(ch + 1, (ch + 1) & 1);
            asm volatile("cp.async.wait_group 1;" ::: "memory");
        } else {
            asm volatile("cp.async.wait_group 0;" ::: "memory");
        }
        __syncthreads();
        uint32_t sA = sb + (ch & 1) * 32768;
        uint32_t sB = sA + 16384;
#pragma unroll
        for (int kk = 0; kk < 4; kk++) {
            uint32_t a[2][4];
#pragma unroll
            for (int mt = 0; mt < 2; mt++) {
                int r = wm*32 + mt*16 + (lane & 7) + ((lane >> 3) & 1) * 8;
                int cch = kk*2 + (lane >> 4);
                ldsm4(a[mt], sA + r*128 + ((cch ^ (r & 7)) << 4));
            }
            uint32_t b[8][2];
#pragma unroll
            for (int np = 0; np < 4; np++) {
                int r = wn*64 + np*16 + (lane & 7) + ((lane >> 4) & 1) * 8;
                int cch = kk*2 + ((lane >> 3) & 1);
                uint32_t d[4];
                ldsm4(d, sB + r*128 + ((cch ^ (r & 7)) << 4));
                b[2*np][0]=d[0]; b[2*np][1]=d[1];
                b[2*np+1][0]=d[2]; b[2*np+1][1]=d[3];
            }
#pragma unroll
            for (int mt = 0; mt < 2; mt++)
#pragma unroll
                for (int nt = 0; nt < 8; nt++)
                    MmaOp<f16>::run(acc[mt][nt], a[mt], b[nt]);
        }
        __syncthreads();
    }

    // fused epilogue: warp owns full 64-col head rows
    int b_ = m0 >> 11;
    int ncol0 = n0 + wn*64;               // 64-aligned head block
    bool isK = ncol0 < 1024;
    int h = (isK ? ncol0 : ncol0 - 1024) >> 6;
    float wv[8][2];
    if (isK) {
#pragma unroll
        for (int nt = 0; nt < 8; nt++) {
            int hd = nt*8 + (lane & 3)*2;
            wv[nt][0] = knw[hd]; wv[nt][1] = knw[hd + 1];
        }
    }
#pragma unroll
    for (int mt = 0; mt < 2; mt++) {
#pragma unroll
        for (int half = 0; half < 2; half++) {
            int mrow = m0 + wm*32 + mt*16 + (lane >> 2) + half*8;
            int s = mrow & 2047;
            size_t rb = (((size_t)(b_*Hv + h))*Sv + s)*64;
            if (isK) {
                float ss = 0.f;
#pragma unroll
                for (int nt = 0; nt < 8; nt++) {
                    float v0 = acc[mt][nt][half*2], v1 = acc[mt][nt][half*2+1];
                    ss += v0*v0 + v1*v1;
                }
                ss += __shfl_xor_sync(0xffffffffu, ss, 1);
                ss += __shfl_xor_sync(0xffffffffu, ss, 2);
                float rinv = rsqrtf(ss / 64.f + 1e-6f);
#pragma unroll
                for (int nt = 0; nt < 8; nt++) {
                    int hd = nt*8 + (lane & 3)*2;
                    float v0 = acc[mt][nt][half*2]   * wv[nt][0] * rinv;
                    float v1 = acc[mt][nt][half*2+1] * wv[nt][1] * rinv;
                    *(__half2*)&keysb[rb + hd] = __floats2half2_rn(v0, v1);
                }
            } else {
#pragma unroll
                for (int nt = 0; nt < 8; nt++) {
                    int hd = nt*8 + (lane & 3)*2;
                    *(float2*)&values[rb + hd] =
                        make_float2(acc[mt][nt][half*2], acc[mt][nt][half*2+1]);
                }
            }
        }
    }
#undef LOAD_KV
}

// ===== Q GEMM: (16384x1024)@(1024x1024), 2-term fp16 (A single, B hi/lo) ====
// fused head-rmsnorm(qnw) -> q fp32 + qhi/qlo bf16
#define Q_SMEM (2*49152)
__global__ void __launch_bounds__(256)
k_gemm_q(const f16* __restrict__ A, const f16* __restrict__ Bhi,
         const f16* __restrict__ Blo, float* __restrict__ qout,
         bf16* __restrict__ qhi, bf16* __restrict__ qlo,
         const float* __restrict__ qnw) {
    extern __shared__ char smem[];
    uint32_t sb = smem_u32(smem);
    int tid = threadIdx.x;
    int wid = tid >> 5, lane = tid & 31;
    int wm = wid >> 1, wn = wid & 1;
    int m0 = blockIdx.y * 128, n0 = blockIdx.x * 128;

    const f16* base_l[3] = { A + (size_t)m0 * Dv,
                             Bhi + (size_t)n0 * Dv, Blo + (size_t)n0 * Dv };
#define LOAD_Q(CH, ST) do {                                                    \
    int _k0 = (CH) * 64;                                                       \
    uint32_t _sb = sb + (ST) * 49152;                                          \
    _Pragma("unroll")                                                          \
    for (int i = 0; i < 12; i++) {                                             \
        int idx = i * 256 + tid;                                               \
        int layer = idx >> 10, rem = idx & 1023;                               \
        int r = rem >> 3, g = rem & 7;                                         \
        const f16* src = base_l[layer] + (size_t)r * Dv + _k0 + g * 8;         \
        cp16(_sb + layer * 16384 + r * 128 + ((g ^ (r & 7)) << 4), src);       \
    }                                                                          \
    asm volatile("cp.async.commit_group;" ::: "memory");                       \
} while (0)

    LOAD_Q(0, 0);
    float acc[2][8][4];
#pragma unroll
    for (int mt = 0; mt < 2; mt++)
#pragma unroll
        for (int nt = 0; nt < 8; nt++)
#pragma unroll
            for (int e = 0; e < 4; e++) acc[mt][nt][e] = 0.f;

    for (int ch = 0; ch < 16; ch++) {
        if (ch < 15) {
            LOAD_Q(ch + 1, (ch + 1) & 1);
            asm volatile("cp.async.wait_group 1;" ::: "memory");
        } else {
            asm volatile("cp.async.wait_group 0;" ::: "memory");
        }
        __syncthreads();
        uint32_t sA = sb + (ch & 1) * 49152;
#pragma unroll
        for (int kk = 0; kk < 4; kk++) {
            uint32_t a[2][4];
#pragma unroll
            for (int mt = 0; mt < 2; mt++) {
                int r = wm*32 + mt*16 + (lane & 7) + ((lane >> 3) & 1) * 8;
                int cch = kk*2 + (lane >> 4);
                ldsm4(a[mt], sA + r*128 + ((cch ^ (r & 7)) << 4));
            }
            uint32_t bh[8][2], bl[8][2];
#pragma unroll
            for (int np = 0; np < 4; np++) {
                int r = wn*64 + np*16 + (lane & 7) + ((lane >> 4) & 1) * 8;
                int cch = kk*2 + ((lane >> 3) & 1);
                uint32_t off = r*128 + ((cch ^ (r & 7)) << 4);
                uint32_t d[4];
                ldsm4(d, sA + 16384 + off);
                bh[2*np][0]=d[0]; bh[2*np][1]=d[1];
                bh[2*np+1][0]=d[2]; bh[2*np+1][1]=d[3];
                ldsm4(d, sA + 32768 + off);
                bl[2*np][0]=d[0]; bl[2*np][1]=d[1];
                bl[2*np+1][0]=d[2]; bl[2*np+1][1]=d[3];
            }
#pragma unroll
            for (int mt = 0; mt < 2; mt++)
#pragma unroll
                for (int nt = 0; nt < 8; nt++) {
                    MmaOp<f16>::run(acc[mt][nt], a[mt], bh[nt]);
                    MmaOp<f16>::run(acc[mt][nt], a[mt], bl[nt]);
                }
        }
        __syncthreads();
    }

    int b_ = m0 >> 11;
    int ncol0 = n0 + wn*64;
    int h = ncol0 >> 6;
    float wv[8][2];
#pragma unroll
    for (int nt = 0; nt < 8; nt++) {
        int hd = nt*8 + (lane & 3)*2;
        wv[nt][0] = qnw[hd]; wv[nt][1] = qnw[hd + 1];
    }
#pragma unroll
    for (int mt = 0; mt < 2; mt++) {
#pragma unroll
        for (int half = 0; half < 2; half++) {
            int mrow = m0 + wm*32 + mt*16 + (lane >> 2) + half*8;
            int s = mrow & 2047;
            size_t rb = (((size_t)(b_*Hv + h))*Sv + s)*64;
            float ss = 0.f;
#pragma unroll
            for (int nt = 0; nt < 8; nt++) {
                float v0 = acc[mt][nt][half*2], v1 = acc[mt][nt][half*2+1];
                ss += v0*v0 + v1*v1;
            }
            ss += __shfl_xor_sync(0xffffffffu, ss, 1);
            ss += __shfl_xor_sync(0xffffffffu, ss, 2);
            float rinv = rsqrtf(ss / 64.f + 1e-6f);
#pragma unroll
            for (int nt = 0; nt < 8; nt++) {
                int hd = nt*8 + (lane & 3)*2;
                float v0 = acc[mt][nt][half*2]   * wv[nt][0] * rinv;
                float v1 = acc[mt][nt][half*2+1] * wv[nt][1] * rinv;
                *(float2*)&qout[rb + hd] = make_float2(v0, v1);
                bf16 h0 = __float2bfloat16(v0), h1 = __float2bfloat16(v1);
                *(__nv_bfloat162*)&qhi[rb + hd] = __nv_bfloat162(h0, h1);
                *(__nv_bfloat162*)&qlo[rb + hd] = __floats2bfloat162_rn(
                    v0 - __bfloat162float(h0), v1 - __bfloat162float(h1));
            }
        }
    }
#undef LOAD_Q
}

// ======== MLP GEMM 1: C[MT,256] = A[MT,64] @ B[256,64]^T (B K-major) ========
template <int MODE, typename T>
__global__ void __launch_bounds__(256)
k_mlp0(const T* __restrict__ Ahi, const T* __restrict__ Alo,
       const T* __restrict__ Bhi, const T* __restrict__ Blo,
       long long ws, T* __restrict__ o1, T* __restrict__ o2) {
    extern __shared__ char sm[];
    uint32_t sb = smem_u32(sm);
    constexpr uint32_t SB = (MODE == 2) ? 16384u : 8192u;
    int tid = threadIdx.x, wid = tid >> 5, lane = tid & 31;
    int wm = wid >> 2, wn = wid & 3;          // 2(M) x 4(N)
    int m0 = blockIdx.x * 64;
    int bh = m0 >> 11;

    {
        const T* Ab = Ahi + (size_t)m0 * 64;
#pragma unroll
        for (int i = 0; i < 2; i++) {
            int idx = i*256 + tid; int r = idx >> 3, g = idx & 7;
            cp16(sb + r*128 + ((g ^ (r & 7)) << 4), Ab + r*64 + g*8);
        }
        if (MODE == 2) {
            const T* A2 = Alo + (size_t)m0 * 64;
#pragma unroll
            for (int i = 0; i < 2; i++) {
                int idx = i*256 + tid; int r = idx >> 3, g = idx & 7;
                cp16(sb + 8192 + r*128 + ((g ^ (r & 7)) << 4), A2 + r*64 + g*8);
            }
        }
        const T* Bb = Bhi + (size_t)bh * ws;
#pragma unroll
        for (int i = 0; i < 8; i++) {
            int idx = i*256 + tid; int r = idx >> 3, g = idx & 7;
            cp16(sb + SB + r*128 + ((g ^ (r & 7)) << 4), Bb + r*64 + g*8);
        }
        if (MODE == 2) {
            const T* B2 = Blo + (size_t)bh * ws;
#pragma unroll
            for (int i = 0; i < 8; i++) {
                int idx = i*256 + tid; int r = idx >> 3, g = idx & 7;
                cp16(sb + SB + 32768 + r*128 + ((g ^ (r & 7)) << 4), B2 + r*64 + g*8);
            }
        }
    }
    asm volatile("cp.async.commit_group;\ncp.async.wait_group 0;" ::: "memory");
    __syncthreads();

    float acc[2][8][4];
#pragma unroll
    for (int mt = 0; mt < 2; mt++)
#pragma unroll
        for (int nt = 0; nt < 8; nt++)
#pragma unroll
            for (int e = 0; e < 4; e++) acc[mt][nt][e] = 0.f;

#pragma unroll
    for (int kk = 0; kk < 4; kk++) {
        uint32_t ah[2][4], al[2][4];
#pragma unroll
        for (int mt = 0; mt < 2; mt++) {
            int r = wm*32 + mt*16 + (lane & 7) + ((lane >> 3) & 1) * 8;
            int cch = kk*2 + (lane >> 4);
            uint32_t off = r*128 + ((cch ^ (r & 7)) << 4);
            ldsm4(ah[mt], sb + off);
            if (MODE == 2) ldsm4(al[mt], sb + 8192 + off);
        }
        uint32_t bh_r[8][2], bl_r[8][2];
#pragma unroll
        for (int np = 0; np < 4; np++) {
            int r = wn*64 + np*16 + (lane & 7) + ((lane >> 4) & 1) * 8;
            int cch = kk*2 + ((lane >> 3) & 1);
            uint32_t off = r*128 + ((cch ^ (r & 7)) << 4);
            uint32_t d[4];
            ldsm4(d, sb + SB + off);
            bh_r[2*np][0]=d[0]; bh_r[2*np][1]=d[1];
            bh_r[2*np+1][0]=d[2]; bh_r[2*np+1][1]=d[3];
            if (MODE == 2) {
                ldsm4(d, sb + SB + 32768 + off);
                bl_r[2*np][0]=d[0]; bl_r[2*np][1]=d[1];
                bl_r[2*np+1][0]=d[2]; bl_r[2*np+1][1]=d[3];
            }
        }
#pragma unroll
        for (int mt = 0; mt < 2; mt++)
#pragma unroll
            for (int nt = 0; nt < 8; nt++) {
                MmaOp<T>::run(acc[mt][nt], ah[mt], bh_r[nt]);
                if (MODE == 2) {
                    MmaOp<T>::run(acc[mt][nt], ah[mt], bl_r[nt]);
                    MmaOp<T>::run(acc[mt][nt], al[mt], bh_r[nt]);
                }
            }
    }

#pragma unroll
    for (int mt = 0; mt < 2; mt++) {
        int mrow = m0 + wm*32 + mt*16 + (lane >> 2);
#pragma unroll
        for (int nt = 0; nt < 8; nt++) {
            int c = wn*64 + nt*8 + (lane & 3) * 2;
#pragma unroll
            for (int half = 0; half < 2; half++) {
                size_t off = (size_t)(mrow + half*8) * 256 + c;
                float v0 = acc[mt][nt][half*2], v1 = acc[mt][nt][half*2 + 1];
                if (MODE == 0) {
                    o1[off] = fromf<T>(v0);          o1[off+1] = fromf<T>(v1);
                    o2[off] = fromf<T>(geluf(v0));   o2[off+1] = fromf<T>(geluf(v1));
                } else if (MODE == 1) {
                    float p0 = tof(o2[off]), p1 = tof(o2[off+1]);
                    o1[off]   = fromf<T>(v0 * gelugrad(p0));
                    o1[off+1] = fromf<T>(v1 * gelugrad(p1));
                } else {
                    float gl0 = geluf(v0), gl1 = geluf(v1);
                    T h0 = fromf<T>(gl0), h1 = fromf<T>(gl1);
                    o1[off] = h0; o1[off+1] = h1;
                    o2[off]   = fromf<T>(gl0 - tof(h0));
                    o2[off+1] = fromf<T>(gl1 - tof(h1));
                }
            }
        }
    }
}

// ======== MLP GEMM 2: C[MT,64] fp32 = A[MT,256] @ B[64,256]^T ==============
template <int MODE, typename T>
__global__ void __launch_bounds__(256)
k_mlp1(const T* __restrict__ Ahi, const T* __restrict__ Alo,
       const T* __restrict__ Bhi, const T* __restrict__ Blo,
       long long ws, float* __restrict__ Cout) {
    extern __shared__ char sm[];
    uint32_t sb = smem_u32(sm);
    constexpr uint32_t SB = (MODE == 1) ? 65536u : 32768u;
    constexpr uint32_t ASTRIDE = (MODE == 1) ? 32768u : 16384u;
    int tid = threadIdx.x, wid = tid >> 5, lane = tid & 31;
    int wm = wid >> 1, wn = wid & 1;          // 4(M) x 2(N)
    int m0 = blockIdx.x * 128;
    int bh = m0 >> 11;

    {
        const T* Bb = Bhi + (size_t)bh * ws;
#pragma unroll
        for (int i = 0; i < 8; i++) {
            int idx = i*256 + tid; int r = idx >> 5, g = idx & 31;
            cp16(sb + SB + r*512 + ((g ^ (r & 7)) << 4), Bb + r*256 + g*8);
        }
        if (MODE == 1) {
            const T* B2 = Blo + (size_t)bh * ws;
#pragma unroll
            for (int i = 0; i < 8; i++) {
                int idx = i*256 + tid; int r = idx >> 5, g = idx & 31;
                cp16(sb + SB + 32768 + r*512 + ((g ^ (r & 7)) << 4), B2 + r*256 + g*8);
            }
        }
    }
#define LA(CH, ST) do {                                                        \
    uint32_t _a = sb + (ST) * ASTRIDE;                                         \
    _Pragma("unroll")                                                          \
    for (int i = 0; i < 4; i++) {                                              \
        int idx = i*256 + tid; int r = idx >> 3, g = idx & 7;                  \
        cp16(_a + r*128 + ((g ^ (r & 7)) << 4),                                \
             Ahi + (size_t)(m0 + r)*256 + (CH)*64 + g*8);                      \
        if (MODE == 1)                                                         \
            cp16(_a + 16384 + r*128 + ((g ^ (r & 7)) << 4),                    \
                 Alo + (size_t)(m0 + r)*256 + (CH)*64 + g*8);                  \
    }                                                                          \
    asm volatile("cp.async.commit_group;" ::: "memory");                       \
} while (0)

    LA(0, 0);
    float acc[2][4][4];
#pragma unroll
    for (int mt = 0; mt < 2; mt++)
#pragma unroll
        for (int nt = 0; nt < 4; nt++)
#pragma unroll
            for (int e = 0; e < 4; e++) acc[mt][nt][e] = 0.f;

    for (int ch = 0; ch < 4; ch++) {
        if (ch < 3) {
            LA(ch + 1, (ch + 1) & 1);
            asm volatile("cp.async.wait_group 1;" ::: "memory");
        } else {
            asm volatile("cp.async.wait_group 0;" ::: "memory");
        }
        __syncthreads();
        uint32_t sA = sb + (ch & 1) * ASTRIDE;
#pragma unroll
        for (int kk = 0; kk < 4; kk++) {
            uint32_t ah[2][4], al[2][4];
#pragma unroll
            for (int mt = 0; mt < 2; mt++) {
                int r = wm*32 + mt*16 + (lane & 7) + ((lane >> 3) & 1) * 8;
                int cch = kk*2 + (lane >> 4);
                uint32_t off = r*128 + ((cch ^ (r & 7)) << 4);
                ldsm4(ah[mt], sA + off);
                if (MODE == 1) ldsm4(al[mt], sA + 16384 + off);
            }
            uint32_t bh_r[4][2], bl_r[4][2];
#pragma unroll
            for (int np = 0; np < 2; np++) {
                int r = wn*32 + np*16 + (lane & 7) + ((lane >> 4) & 1) * 8;
                int kg = ch*8 + kk*2 + ((lane >> 3) & 1);
                uint32_t off = r*512 + ((kg ^ (r & 7)) << 4);
                uint32_t d[4];
                ldsm4(d, sb + SB + off);
                bh_r[2*np][0]=d[0]; bh_r[2*np][1]=d[1];
                bh_r[2*np+1][0]=d[2]; bh_r[2*np+1][1]=d[3];
                if (MODE == 1) {
                    ldsm4(d, sb + SB + 32768 + off);
                    bl_r[2*np][0]=d[0]; bl_r[2*np][1]=d[1];
                    bl_r[2*np+1][0]=d[2]; bl_r[2*np+1][1]=d[3];
                }
            }
#pragma unroll
            for (int mt = 0; mt < 2; mt++)
#pragma unroll
                for (int nt = 0; nt < 4; nt++) {
                    MmaOp<T>::run(acc[mt][nt], ah[mt], bh_r[nt]);
                    if (MODE == 1) {
                        MmaOp<T>::run(acc[mt][nt], ah[mt], bl_r[nt]);
                        MmaOp<T>::run(acc[mt][nt], al[mt], bh_r[nt]);
                    }
                }
        }
        __syncthreads();
    }
#pragma unroll
    for (int mt = 0; mt < 2; mt++) {
        int mrow = m0 + wm*32 + mt*16 + (lane >> 2);
#pragma unroll
        for (int nt = 0; nt < 4; nt++) {
            int c = wn*32 + nt*8 + (lane & 3) * 2;
            *(float2*)&Cout[(size_t)mrow*64 + c]     = make_float2(acc[mt][nt][0], acc[mt][nt][1]);
            *(float2*)&Cout[(size_t)(mrow+8)*64 + c] = make_float2(acc[mt][nt][2], acc[mt][nt][3]);
        }
    }
#undef LA
}

// ======== gradT ============================================================
template <int MI, int NO>
__global__ void __launch_bounds__(256)
k_gradmma(const f16* __restrict__ A, const f16* __restrict__ Bm,
          float* __restrict__ G) {
    __shared__ __align__(16) char sm[32768];
    uint32_t sb = smem_u32(sm);
    int tid = threadIdx.x, wid = tid >> 5, lane = tid & 31;
    int wm = wid >> 2, wn = wid & 3;
    int bh = blockIdx.z;
    int m0 = blockIdx.y * 64, n0 = blockIdx.x * 64;
    const f16* Ab = A  + ((size_t)bh * Sv) * MI + m0;
    const f16* Bb = Bm + ((size_t)bh * Sv) * NO + n0;

#define LG(ST, S0) do {                                                        \
    _Pragma("unroll")                                                          \
    for (int i = 0; i < 2; i++) {                                              \
        int idx = i*256 + tid; int r = idx >> 3, g = idx & 7;                  \
        cp16(sb + (ST)*8192 + r*128 + ((g ^ (r & 7)) << 4),                    \
             Ab + (size_t)((S0) + r)*MI + g*8);                                \
        cp16(sb + 16384 + (ST)*8192 + r*128 + ((g ^ (r & 7)) << 4),            \
             Bb + (size_t)((S0) + r)*NO + g*8);                                \
    }                                                                          \
    asm volatile("cp.async.commit_group;" ::: "memory");                       \
} while (0)

    LG(0, 0);
    float acc[2][2][4];
#pragma unroll
    for (int mt = 0; mt < 2; mt++)
#pragma unroll
        for (int nt = 0; nt < 2; nt++)
#pragma unroll
            for (int e = 0; e < 4; e++) acc[mt][nt][e] = 0.f;

    for (int st = 0; st < 32; st++) {
        if (st < 31) {
            LG((st + 1) & 1, (st + 1) * 64);
            asm volatile("cp.async.wait_group 1;" ::: "memory");
        } else {
            asm volatile("cp.async.wait_group 0;" ::: "memory");
        }
        __syncthreads();
        uint32_t sA = sb + (st & 1) * 8192;
        uint32_t sB = sb + 16384 + (st & 1) * 8192;
#pragma unroll
        for (int kk = 0; kk < 4; kk++) {
            uint32_t aT[2][4];
#pragma unroll
            for (int mt = 0; mt < 2; mt++) {
                int row = kk*16 + (lane & 7) + ((lane >> 4) & 1) * 8;
                int cg = wm*4 + mt*2 + ((lane >> 3) & 1);
                ldsm4t(aT[mt], sA + row*128 + ((cg ^ (row & 7)) << 4));
            }
            int row = kk*16 + (lane & 7) + ((lane >> 3) & 1) * 8;
            int cg = wn*2 + (lane >> 4);
            uint32_t d[4];
            ldsm4t(d, sB + row*128 + ((cg ^ (row & 7)) << 4));
            uint32_t bT[2][2] = {{d[0], d[1]}, {d[2], d[3]}};
#pragma unroll
            for (int mt = 0; mt < 2; mt++)
#pragma unroll
                for (int nt = 0; nt < 2; nt++)
                    MmaOp<f16>::run(acc[mt][nt], aT[mt], bT[nt]);
        }
        __syncthreads();
    }
#pragma unroll
    for (int mt = 0; mt < 2; mt++) {
        int m = m0 + wm*32 + mt*16 + (lane >> 2);
#pragma unroll
        for (int nt = 0; nt < 2; nt++) {
            int n = n0 + wn*16 + nt*8 + (lane & 3) * 2;
            *(float2*)&G[((size_t)bh*MI + m)*NO + n]     = make_float2(acc[mt][nt][0], acc[mt][nt][1]);
            *(float2*)&G[((size_t)bh*MI + m + 8)*NO + n] = make_float2(acc[mt][nt][2], acc[mt][nt][3]);
        }
    }
#undef LG
}

// ---------- fused pf_rmsnorm fwd+bwd for the store loss gradient ------------
__global__ void k_dh(const f16* __restrict__ keysb, f16* __restrict__ dhb) {
    int r = blockIdx.x * 8 + (threadIdx.x >> 5);
    int lane = threadIdx.x & 31;
    size_t base = (size_t)r * 64;
    float h0 = g_pre1[base + lane], h1 = g_pre1[base + lane + 32];
    float ss = h0*h0 + h1*h1;
#pragma unroll
    for (int o = 16; o > 0; o >>= 1) ss += __shfl_xor_sync(0xffffffffu, ss, o);
    float rms = sqrtf(ss / 64.f + 1e-8f);
    float hn0 = h0 / rms, hn1 = h1 / rms;
    float t = g_theta[r];
    float k0 = __half2float(keysb[base + lane]);
    float k1 = __half2float(keysb[base + lane + 32]);
    float dp0 = 2.f * t * ((hn0 + k0) - g_values[base + lane]);
    float dp1 = 2.f * t * ((hn1 + k1) - g_values[base + lane + 32]);
    float dy = dp0*hn0 + dp1*hn1;
#pragma unroll
    for (int o = 16; o > 0; o >>= 1) dy += __shfl_xor_sync(0xffffffffu, dy, o);
    dhb[base + lane]      = __float2half((dp0 - hn0 * dy / 64.f) / rms);
    dhb[base + lane + 32] = __float2half((dp1 - hn1 * dy / 64.f) / rms);
}

// ---------------- gates: alpha, theta (reads fp16 xn) -----------------------
__global__ void __launch_bounds__(256)
k_gates(const f16* __restrict__ xn,
        const float* __restrict__ aw, const float* __restrict__ ab,
        const float* __restrict__ tw, const float* __restrict__ tb) {
    __shared__ float Xs[64][128];
    __shared__ float Ws[64][32];
    int m0 = blockIdx.x * 128;
    int tid = threadIdx.x;
    int rg = tid >> 3, cg = tid & 7;
    float acc[4][4] = {};
    for (int k0 = 0; k0 < 1024; k0 += 64) {
#pragma unroll
        for (int i = 0; i < 4; i++) {
            int idx = tid + i*256;
            int r = idx >> 3, c8 = idx & 7;
            size_t ga = (size_t)(m0 + r)*1024 + k0 + c8*8;
            uint4 vh = *(const uint4*)&xn[ga];
            __half2 h2[4];
            *(uint4*)h2 = vh;
#pragma unroll
            for (int j = 0; j < 4; j++) {
                float2 fh = __half22float2(h2[j]);
                Xs[c8*8 + 2*j][r]     = fh.x;
                Xs[c8*8 + 2*j + 1][r] = fh.y;
            }
        }
#pragma unroll
        for (int i = 0; i < 2; i++) {
            int idx = tid + i*256;
            int r = idx >> 3, c4 = idx & 7;
            const float* src = (c4 < 4) ? (aw + (size_t)(k0 + r)*16 + c4*4)
                                        : (tw + (size_t)(k0 + r)*16 + (c4 - 4)*4);
            *(float4*)&Ws[r][c4*4] = *(const float4*)src;
        }
        __syncthreads();
#pragma unroll
        for (int k = 0; k < 64; k++) {
            float ra[4], rb[4];
#pragma unroll
            for (int i = 0; i < 4; i++) ra[i] = Xs[k][rg*4 + i];
#pragma unroll
            for (int j = 0; j < 4; j++) rb[j] = Ws[k][cg*4 + j];
#pragma unroll
            for (int i = 0; i < 4; i++)
#pragma unroll
                for (int j = 0; j < 4; j++) acc[i][j] += ra[i] * rb[j];
        }
        __syncthreads();
    }
#pragma unroll
    for (int i = 0; i < 4; i++) {
        int m = m0 + rg*4 + i;
        int b = m >> 11, s = m & 2047;
#pragma unroll
        for (int j = 0; j < 4; j++) {
            int c = cg*4 + j;
            int h = c & 15;
            size_t off = ((size_t)(b*Hv + h))*Sv + s;
            if (c < 16) g_alpha[off] = 1.f / (1.f + expf(-(acc[i][j] + ab[h])));
            else        g_theta[off] = 0.01f / (1.f + expf(-(acc[i][j] + tb[h])));
        }
    }
}

// ---------------- per-bh reductions -----------------------------------------
__global__ void k_amean() {
    int bh = blockIdx.x; int tid = threadIdx.x;
    float s = 0.f;
    for (int i = tid; i < Sv; i += 256) s += g_alpha[(size_t)bh*Sv + i];
#pragma unroll
    for (int o = 16; o > 0; o >>= 1) s += __shfl_xor_sync(0xffffffffu, s, o);
    __shared__ float red[8];
    if ((tid & 31) == 0) red[tid >> 5] = s;
    __syncthreads();
    if (tid == 0) {
        float t = 0.f;
#pragma unroll
        for (int i = 0; i < 8; i++) t += red[i];
        g_amean[bh] = t / (float)Sv;
    }
}

__global__ void k_clip() {
    int bh = blockIdx.x; int tid = threadIdx.x;
    const float* a = g_g0 + (size_t)bh * 16384;
    const float* b = g_g1 + (size_t)bh * 16384;
    float s = 0.f;
    for (int i = tid; i < 16384; i += 256) {
        float v = a[i]; s += v*v;
        v = b[i]; s += v*v;
    }
#pragma unroll
    for (int o = 16; o > 0; o >>= 1) s += __shfl_xor_sync(0xffffffffu, s, o);
    __shared__ float red[8];
    if ((tid & 31) == 0) red[tid >> 5] = s;
    __syncthreads();
    if (tid == 0) {
        float t = 0.f;
#pragma unroll
        for (int i = 0; i < 8; i++) t += red[i];
        float c = 10.f / (sqrtf(t) + 1e-6f);
        g_coef[bh] = c < 1.f ? c : 1.f;
    }
}

// ---------------- weight prep + update --------------------------------------
__global__ void k_tr(const float* __restrict__ src, float* __restrict__ dstF,
                     f16* __restrict__ dstB, int R, int C) {
    int idx = blockIdx.x * 256 + threadIdx.x;
    if (idx >= R*C) return;
    int c = idx / R, r = idx % R;
    float v = src[r*C + c];
    dstF[idx] = v;
    dstB[idx] = __float2half(v);
}
__global__ void k_cpb(const float* __restrict__ s, f16* __restrict__ d, int n) {
    int idx = blockIdx.x * 256 + threadIdx.x;
    if (idx < n) d[idx] = __float2half(s[idx]);
}
__global__ void k_newwT(const float* __restrict__ WT, const float* __restrict__ gT,
                        bf16* __restrict__ ohi, bf16* __restrict__ olo) {
    size_t idx = (size_t)blockIdx.x * 256 + threadIdx.x;
    int bh = (int)(idx >> 14); int e = (int)(idx & 16383);
    float w = WT[e];
    float nw = (1.f - g_amean[bh]) * w - g_coef[bh] * gT[idx];
    if (!isfinite(nw)) nw = w;
    bf16 h = __float2bfloat16(nw);
    ohi[idx] = h;
    olo[idx] = __float2bfloat16(nw - __bfloat162float(h));
}

// ---------------- retrieve epilogue -----------------------------------------
__global__ void k_final(float* __restrict__ out) {
    int r = blockIdx.x * 8 + (threadIdx.x >> 5);
    int lane = threadIdx.x & 31;
    size_t base = (size_t)r * 64;
    float h0 = g_pre1[base + lane], h1 = g_pre1[base + lane + 32];
    if (!isfinite(h0)) h0 = 0.f;
    if (!isfinite(h1)) h1 = 0.f;
    float ss = h0*h0 + h1*h1;
#pragma unroll
    for (int o = 16; o > 0; o >>= 1) ss += __shfl_xor_sync(0xffffffffu, ss, o);
    float rms = sqrtf(ss / 64.f + 1e-8f);
    float o0 = h0 / rms + g_q[base + lane];
    float o1 = h1 / rms + g_q[base + lane + 32];
    int bh = r >> 11, s = r & 2047;
    int b = bh >> 4, hh = bh & 15;
    size_t ob = ((size_t)(b*Sv + s))*Dv + hh*64;
    out[ob + lane]      = o0;
    out[ob + lane + 32] = o1;
}

// ============================================================================
extern "C" void kernel_launch(void* const* d_in, const int* in_sizes, int n_in,
                              void* d_out, int out_size) {
    (void)in_sizes; (void)n_in; (void)out_size;
    const float* x   = (const float*)d_in[0];
    const float* W_K = (const float*)d_in[1];
    const float* W_V = (const float*)d_in[2];
    const float* W_Q = (const float*)d_in[3];
    const float* mW0 = (const float*)d_in[4];
    const float* mW1 = (const float*)d_in[5];
    const float* knw = (const float*)d_in[6];
    const float* qnw = (const float*)d_in[7];
    const float* snw = (const float*)d_in[8];
    const float* rnw = (const float*)d_in[9];
    const float* aw  = (const float*)d_in[10];
    const float* ab  = (const float*)d_in[11];
    const float* tw  = (const float*)d_in[12];
    const float* tb  = (const float*)d_in[13];
    float* out = (float*)d_out;

    f16 *xnh, *wkv, *wqhi, *wqlo, *keysb, *dhb, *mW0Tb, *mW1Tb, *mW1b;
    bf16 *qhi, *qlo, *nW0Thi, *nW0Tlo, *nW1Thi, *nW1Tlo;
    float *values, *q, *pre1, *g0p, *g1p, *mW0T, *mW1T;
    char* pool;
    cudaGetSymbolAddress((void**)&xnh,    g_xnh);
    cudaGetSymbolAddress((void**)&wkv,    g_wkv);
    cudaGetSymbolAddress((void**)&wqhi,   g_wqhi);
    cudaGetSymbolAddress((void**)&wqlo,   g_wqlo);
    cudaGetSymbolAddress((void**)&values, g_values);
    cudaGetSymbolAddress((void**)&q,      g_q);
    cudaGetSymbolAddress((void**)&pre1,   g_pre1);
    cudaGetSymbolAddress((void**)&keysb,  g_keysb);
    cudaGetSymbolAddress((void**)&qhi,    g_qhi);
    cudaGetSymbolAddress((void**)&qlo,    g_qlo);
    cudaGetSymbolAddress((void**)&dhb,    g_dhb);
    cudaGetSymbolAddress((void**)&pool,   g_pool);
    cudaGetSymbolAddress((void**)&g0p,    g_g0);
    cudaGetSymbolAddress((void**)&g1p,    g_g1);
    cudaGetSymbolAddress((void**)&mW0T,   g_mW0T);
    cudaGetSymbolAddress((void**)&mW1T,   g_mW1T);
    cudaGetSymbolAddress((void**)&mW0Tb,  g_mW0Tb);
    cudaGetSymbolAddress((void**)&mW1Tb,  g_mW1Tb);
    cudaGetSymbolAddress((void**)&mW1b,   g_mW1b);
    cudaGetSymbolAddress((void**)&nW0Thi, g_nW0Thi);
    cudaGetSymbolAddress((void**)&nW0Tlo, g_nW0Tlo);
    cudaGetSymbolAddress((void**)&nW1Thi, g_nW1Thi);
    cudaGetSymbolAddress((void**)&nW1Tlo, g_nW1Tlo);

    f16* pre0h = (f16*)(pool);
    f16* h1h   = (f16*)(pool + 134217728);
    f16* dh0h  = (f16*)(pool + 268435456);
    bf16* h1rhi = (bf16*)(pool);              // aliases pre0h (dead by then)
    bf16* h1rlo = (bf16*)(pool + 268435456);  // aliases dh0h (dead by then)

    cudaFuncSetAttribute(k_gemm_kv, cudaFuncAttributeMaxDynamicSharedMemorySize, KV_SMEM);
    cudaFuncSetAttribute(k_gemm_q,  cudaFuncAttributeMaxDynamicSharedMemorySize, Q_SMEM);
    cudaFuncSetAttribute((k_mlp0<0, f16>), cudaFuncAttributeMaxDynamicSharedMemorySize, 40960);
    cudaFuncSetAttribute((k_mlp0<1, f16>), cudaFuncAttributeMaxDynamicSharedMemorySize, 40960);
    cudaFuncSetAttribute((k_mlp0<2, bf16>), cudaFuncAttributeMaxDynamicSharedMemorySize, 81920);
    cudaFuncSetAttribute((k_mlp1<0, f16>), cudaFuncAttributeMaxDynamicSharedMemorySize, 65536);
    cudaFuncSetAttribute((k_mlp1<1, bf16>), cudaFuncAttributeMaxDynamicSharedMemorySize, 131072);

    dim3 gws(32, 32), bws(32, 8);

    // ---- weight prep (independent) ----
    k_tr<<<64, 256>>>(mW0, mW0T, mW0Tb, HDv, HIDv);   // -> [256][64]
    k_tr<<<64, 256>>>(mW1, mW1T, mW1Tb, HIDv, HDv);   // -> [64][256]
    k_cpb<<<64, 256>>>(mW1, mW1b, HIDv*HDv);

    // ---- store path ----
    k_rmsnorm16<<<Mv, 256>>>(x, snw, xnh);
    k_wt16<<<gws, bws>>>(W_K, wkv);
    k_wt16<<<gws, bws>>>(W_V, wkv + (size_t)Dv*Dv);
    k_gemm_kv<<<dim3(16, 128), 256, KV_SMEM>>>(xnh, wkv, keysb, values, knw);
    k_gates<<<Mv/128, 256>>>(xnh, aw, ab, tw, tb);
    k_amean<<<BHv, 256>>>();

    k_mlp0<0, f16><<<MTv/64, 256, 40960>>>(keysb, nullptr, mW0Tb, nullptr, 0, pre0h, h1h);
    k_mlp1<0, f16><<<MTv/128, 256, 65536>>>(h1h, nullptr, mW1Tb, nullptr, 0, pre1);
    k_dh<<<MTv/8, 256>>>(keysb, dhb);
    k_mlp0<1, f16><<<MTv/64, 256, 40960>>>(dhb, nullptr, mW1b, nullptr, 0, dh0h, pre0h);

    k_gradmma<HDv, HIDv><<<dim3(4, 1, BHv), 256>>>(dhb, h1h, g1p);     // g1^T [64][256]
    k_gradmma<HIDv, HDv><<<dim3(1, 4, BHv), 256>>>(dh0h, keysb, g0p);  // g0^T [256][64]
    k_clip<<<BHv, 256>>>();
    k_newwT<<<(BHv*16384)/256, 256>>>(mW0T, g0p, nW0Thi, nW0Tlo);
    k_newwT<<<(BHv*16384)/256, 256>>>(mW1T, g1p, nW1Thi, nW1Tlo);

    // ---- retrieve path ----
    k_rmsnorm16<<<Mv, 256>>>(x, rnw, xnh);
    k_wt2<<<gws, bws>>>(W_Q, wqhi, wqlo);
    k_gemm_q<<<dim3(8, 128), 256, Q_SMEM>>>(xnh, wqhi, wqlo, q, qhi, qlo, qnw);
    k_mlp0<2, bf16><<<MTv/64, 256, 81920>>>(qhi, qlo, nW0Thi, nW0Tlo,
                                            (long long)HIDv*HDv, h1rhi, h1rlo);
    k_mlp1<1, bf16><<<MTv/128, 256, 131072>>>(h1rhi, h1rlo, nW1Thi, nW1Tlo,
                                              (long long)HDv*HIDv, pre1);
    k_final<<<MTv/8, 256>>>(out);
}

// round 10
// speedup vs baseline: 2.0249x; 2.0249x over previous
#include <cuda_runtime.h>
#include <cuda_bf16.h>
#include <cuda_fp16.h>
#include <math.h>
#include <stdint.h>

// Problem constants
#define Bv   8
#define Sv   2048
#define Dv   1024
#define Hv   16
#define HDv  64
#define HIDv 256
#define BHv  128               // B*H
#define Mv   (Bv*Sv)           // 16384 rows of x
#define MTv  (BHv*Sv)          // 262144 rows per-head

typedef __nv_bfloat16 bf16;
typedef __half f16;

// ------------------------- scratch (device globals) -------------------------
__device__ f16  g_xnh[Mv*Dv];         // 32 MB  (normed x, fp16; store then retrieve)
__device__ f16  g_wkv[2*Dv*Dv];       // 4 MB   (W_K^T | W_V^T fp16, [2048][1024])
__device__ f16  g_wqhi[Dv*Dv];        // 2 MB
__device__ f16  g_wqlo[Dv*Dv];        // 2 MB
__device__ float g_values[MTv*HDv];   // 64 MB
__device__ float g_q[MTv*HDv];        // 64 MB (normed q, fp32)
__device__ float g_pre1[MTv*HDv];     // 64 MB
__device__ f16  g_keysb[MTv*HDv];     // 32 MB (normed keys, fp16)
__device__ f16  g_qh[MTv*HDv];        // 32 MB (normed q, fp16)
__device__ f16  g_dhb[MTv*HDv];       // 32 MB
// pooled scratch: pre0h@0, h1h@128M, dh0h@256M; retrieve: h1rh@0
__device__ __align__(256) char g_pool[402653184];   // 384 MB
__device__ float g_alpha[BHv*Sv];
__device__ float g_theta[BHv*Sv];
__device__ float g_amean[BHv];
__device__ float g_coef[BHv];
__device__ float g_g0[BHv*HIDv*HDv];  // g0^T [bh][256][64] fp32
__device__ float g_g1[BHv*HDv*HIDv];  // g1^T [bh][64][256] fp32
__device__ float g_mW0T[HIDv*HDv];    __device__ f16 g_mW0Tb[HIDv*HDv];
__device__ float g_mW1T[HDv*HIDv];    __device__ f16 g_mW1Tb[HDv*HIDv];
__device__ f16 g_mW1b[HIDv*HDv];
__device__ f16 g_nW0Thi[BHv*HIDv*HDv], g_nW0Tlo[BHv*HIDv*HDv];
__device__ f16 g_nW1Thi[BHv*HDv*HIDv], g_nW1Tlo[BHv*HDv*HIDv];

// ========================= mma.sync helpers =================================
__device__ __forceinline__ uint32_t smem_u32(const void* p) {
    uint32_t a;
    asm("{ .reg .u64 t; cvta.to.shared.u64 t, %1; cvt.u32.u64 %0, t; }"
        : "=r"(a) : "l"(p));
    return a;
}
__device__ __forceinline__ void ldsm4(uint32_t* d, uint32_t addr) {
    asm volatile("ldmatrix.sync.aligned.m8n8.x4.shared.b16 {%0,%1,%2,%3}, [%4];"
                 : "=r"(d[0]), "=r"(d[1]), "=r"(d[2]), "=r"(d[3]) : "r"(addr));
}
__device__ __forceinline__ void ldsm4t(uint32_t* d, uint32_t addr) {
    asm volatile("ldmatrix.sync.aligned.m8n8.x4.trans.shared.b16 {%0,%1,%2,%3}, [%4];"
                 : "=r"(d[0]), "=r"(d[1]), "=r"(d[2]), "=r"(d[3]) : "r"(addr));
}
__device__ __forceinline__ void mma_h(float* c, const uint32_t* a, const uint32_t* b) {
    asm volatile("mma.sync.aligned.m16n8k16.row.col.f32.f16.f16.f32 "
                 "{%0,%1,%2,%3}, {%4,%5,%6,%7}, {%8,%9}, {%0,%1,%2,%3};"
                 : "+f"(c[0]), "+f"(c[1]), "+f"(c[2]), "+f"(c[3])
                 : "r"(a[0]), "r"(a[1]), "r"(a[2]), "r"(a[3]), "r"(b[0]), "r"(b[1]));
}
__device__ __forceinline__ void cp16(uint32_t dst, const void* src) {
    asm volatile("cp.async.cg.shared.global [%0], [%1], 16;" :: "r"(dst), "l"(src) : "memory");
}
__device__ __forceinline__ float geluf(float v) {
    return 0.5f * v * (1.f + erff(v * 0.70710678118654752f));
}
__device__ __forceinline__ float gelugrad(float p) {
    float cdf = 0.5f * (1.f + erff(p * 0.70710678118654752f));
    float pdf = expf(-0.5f * p * p) * 0.3989422804014327f;
    return cdf + p * pdf;
}

// ---------------- rmsnorm over D=1024 rows, emit fp16 -----------------------
__global__ void k_rmsnorm16(const float* __restrict__ x, const float* __restrict__ w,
                            f16* __restrict__ o) {
    int row = blockIdx.x;
    const float* xr = x + (size_t)row * Dv;
    int tid = threadIdx.x;  // 256
    float v[4]; float ss = 0.f;
#pragma unroll
    for (int i = 0; i < 4; i++) { v[i] = xr[tid + i*256]; ss += v[i]*v[i]; }
#pragma unroll
    for (int o2 = 16; o2 > 0; o2 >>= 1) ss += __shfl_xor_sync(0xffffffffu, ss, o2);
    __shared__ float red[8];
    __shared__ float rinv;
    if ((tid & 31) == 0) red[tid >> 5] = ss;
    __syncthreads();
    if (tid == 0) {
        float t = 0.f;
#pragma unroll
        for (int i = 0; i < 8; i++) t += red[i];
        rinv = rsqrtf(t / (float)Dv + 1e-6f);
    }
    __syncthreads();
    float r = rinv;
#pragma unroll
    for (int i = 0; i < 4; i++)
        o[(size_t)row*Dv + tid + i*256] = __float2half(v[i] * w[tid + i*256] * r);
}

// ---------------- transpose weight -> fp16 (single) -------------------------
__global__ void k_wt16(const float* __restrict__ W, f16* __restrict__ T) {
    __shared__ float t[32][33];
    int k0 = blockIdx.y * 32, n0 = blockIdx.x * 32;
    int tx = threadIdx.x, ty = threadIdx.y;   // (32, 8)
#pragma unroll
    for (int r = 0; r < 4; r++)
        t[ty + r*8][tx] = W[(size_t)(k0 + ty + r*8)*Dv + n0 + tx];
    __syncthreads();
#pragma unroll
    for (int r = 0; r < 4; r++)
        T[(size_t)(n0 + ty + r*8)*Dv + k0 + tx] = __float2half(t[tx][ty + r*8]);
}

// ---------------- transpose weight -> fp16 hi/lo -----------------------------
__global__ void k_wt2(const float* __restrict__ W,
                      f16* __restrict__ Thi, f16* __restrict__ Tlo) {
    __shared__ float t[32][33];
    int k0 = blockIdx.y * 32, n0 = blockIdx.x * 32;
    int tx = threadIdx.x, ty = threadIdx.y;
#pragma unroll
    for (int r = 0; r < 4; r++)
        t[ty + r*8][tx] = W[(size_t)(k0 + ty + r*8)*Dv + n0 + tx];
    __syncthreads();
#pragma unroll
    for (int r = 0; r < 4; r++) {
        float v = t[tx][ty + r*8];
        f16 h = __float2half(v);
        size_t off = (size_t)(n0 + ty + r*8)*Dv + k0 + tx;
        Thi[off] = h;
        Tlo[off] = __float2half(v - __half2float(h));
    }
}

// ===== fused K+V GEMM: (16384x1024)@(1024x2048) fp16 single-pass ============
#define KV_SMEM (2*32768)
__global__ void __launch_bounds__(256)
k_gemm_kv(const f16* __restrict__ A, const f16* __restrict__ Bw,
          f16* __restrict__ keysb, float* __restrict__ values,
          const float* __restrict__ knw) {
    extern __shared__ char smem[];
    uint32_t sb = smem_u32(smem);
    int tid = threadIdx.x;
    int wid = tid >> 5, lane = tid & 31;
    int wm = wid >> 1, wn = wid & 1;          // 4(M) x 2(N)
    int m0 = blockIdx.y * 128, n0 = blockIdx.x * 128;

#define LOAD_KV(CH, ST) do {                                                   \
    int _k0 = (CH) * 64;                                                       \
    uint32_t _sb = sb + (ST) * 32768;                                          \
    _Pragma("unroll")                                                          \
    for (int i = 0; i < 8; i++) {                                              \
        int idx = i * 256 + tid;                                               \
        int layer = idx >> 10, rem = idx & 1023;                               \
        int r = rem >> 3, g = rem & 7;                                         \
        const f16* src = layer ? Bw + (size_t)(n0 + r) * Dv + _k0 + g * 8      \
                               : A  + (size_t)(m0 + r) * Dv + _k0 + g * 8;     \
        cp16(_sb + layer * 16384 + r * 128 + ((g ^ (r & 7)) << 4), src);       \
    }                                                                          \
    asm volatile("cp.async.commit_group;" ::: "memory");                       \
} while (0)

    LOAD_KV(0, 0);
    float acc[2][8][4];
#pragma unroll
    for (int mt = 0; mt < 2; mt++)
#pragma unroll
        for (int nt = 0; nt < 8; nt++)
#pragma unroll
            for (int e = 0; e < 4; e++) acc[mt][nt][e] = 0.f;

    for (int ch = 0; ch < 16; ch++) {
        if (ch < 15) {
            LOAD_KV(ch + 1, (ch + 1) & 1);
            asm volatile("cp.async.wait_group 1;" ::: "memory");
        } else {
            asm volatile("cp.async.wait_group 0;" ::: "memory");
        }
        __syncthreads();
        uint32_t sA = sb + (ch & 1) * 32768;
        uint32_t sB = sA + 16384;
#pragma unroll
        for (int kk = 0; kk < 4; kk++) {
            uint32_t a[2][4];
#pragma unroll
            for (int mt = 0; mt < 2; mt++) {
                int r = wm*32 + mt*16 + (lane & 7) + ((lane >> 3) & 1) * 8;
                int cch = kk*2 + (lane >> 4);
                ldsm4(a[mt], sA + r*128 + ((cch ^ (r & 7)) << 4));
            }
            uint32_t b[8][2];
#pragma unroll
            for (int np = 0; np < 4; np++) {
                int r = wn*64 + np*16 + (lane & 7) + ((lane >> 4) & 1) * 8;
                int cch = kk*2 + ((lane >> 3) & 1);
                uint32_t d[4];
                ldsm4(d, sB + r*128 + ((cch ^ (r & 7)) << 4));
                b[2*np][0]=d[0]; b[2*np][1]=d[1];
                b[2*np+1][0]=d[2]; b[2*np+1][1]=d[3];
            }
#pragma unroll
            for (int mt = 0; mt < 2; mt++)
#pragma unroll
                for (int nt = 0; nt < 8; nt++)
                    mma_h(acc[mt][nt], a[mt], b[nt]);
        }
        __syncthreads();
    }

    // fused epilogue: warp owns full 64-col head rows
    int b_ = m0 >> 11;
    int ncol0 = n0 + wn*64;               // 64-aligned head block
    bool isK = ncol0 < 1024;
    int h = (isK ? ncol0 : ncol0 - 1024) >> 6;
    float wv[8][2];
    if (isK) {
#pragma unroll
        for (int nt = 0; nt < 8; nt++) {
            int hd = nt*8 + (lane & 3)*2;
            wv[nt][0] = knw[hd]; wv[nt][1] = knw[hd + 1];
        }
    }
#pragma unroll
    for (int mt = 0; mt < 2; mt++) {
#pragma unroll
        for (int half = 0; half < 2; half++) {
            int mrow = m0 + wm*32 + mt*16 + (lane >> 2) + half*8;
            int s = mrow & 2047;
            size_t rb = (((size_t)(b_*Hv + h))*Sv + s)*64;
            if (isK) {
                float ss = 0.f;
#pragma unroll
                for (int nt = 0; nt < 8; nt++) {
                    float v0 = acc[mt][nt][half*2], v1 = acc[mt][nt][half*2+1];
                    ss += v0*v0 + v1*v1;
                }
                ss += __shfl_xor_sync(0xffffffffu, ss, 1);
                ss += __shfl_xor_sync(0xffffffffu, ss, 2);
                float rinv = rsqrtf(ss / 64.f + 1e-6f);
#pragma unroll
                for (int nt = 0; nt < 8; nt++) {
                    int hd = nt*8 + (lane & 3)*2;
                    float v0 = acc[mt][nt][half*2]   * wv[nt][0] * rinv;
                    float v1 = acc[mt][nt][half*2+1] * wv[nt][1] * rinv;
                    *(__half2*)&keysb[rb + hd] = __floats2half2_rn(v0, v1);
                }
            } else {
#pragma unroll
                for (int nt = 0; nt < 8; nt++) {
                    int hd = nt*8 + (lane & 3)*2;
                    *(float2*)&values[rb + hd] =
                        make_float2(acc[mt][nt][half*2], acc[mt][nt][half*2+1]);
                }
            }
        }
    }
#undef LOAD_KV
}

// ===== Q GEMM: (16384x1024)@(1024x1024), 2-term fp16 (A single, B hi/lo) ====
// fused head-rmsnorm(qnw) -> q fp32 + qh fp16
#define Q_SMEM (2*49152)
__global__ void __launch_bounds__(256)
k_gemm_q(const f16* __restrict__ A, const f16* __restrict__ Bhi,
         const f16* __restrict__ Blo, float* __restrict__ qout,
         f16* __restrict__ qh, const float* __restrict__ qnw) {
    extern __shared__ char smem[];
    uint32_t sb = smem_u32(smem);
    int tid = threadIdx.x;
    int wid = tid >> 5, lane = tid & 31;
    int wm = wid >> 1, wn = wid & 1;
    int m0 = blockIdx.y * 128, n0 = blockIdx.x * 128;

    const f16* base_l[3] = { A + (size_t)m0 * Dv,
                             Bhi + (size_t)n0 * Dv, Blo + (size_t)n0 * Dv };
#define LOAD_Q(CH, ST) do {                                                    \
    int _k0 = (CH) * 64;                                                       \
    uint32_t _sb = sb + (ST) * 49152;                                          \
    _Pragma("unroll")                                                          \
    for (int i = 0; i < 12; i++) {                                             \
        int idx = i * 256 + tid;                                               \
        int layer = idx >> 10, rem = idx & 1023;                               \
        int r = rem >> 3, g = rem & 7;                                         \
        const f16* src = base_l[layer] + (size_t)r * Dv + _k0 + g * 8;         \
        cp16(_sb + layer * 16384 + r * 128 + ((g ^ (r & 7)) << 4), src);       \
    }                                                                          \
    asm volatile("cp.async.commit_group;" ::: "memory");                       \
} while (0)

    LOAD_Q(0, 0);
    float acc[2][8][4];
#pragma unroll
    for (int mt = 0; mt < 2; mt++)
#pragma unroll
        for (int nt = 0; nt < 8; nt++)
#pragma unroll
            for (int e = 0; e < 4; e++) acc[mt][nt][e] = 0.f;

    for (int ch = 0; ch < 16; ch++) {
        if (ch < 15) {
            LOAD_Q(ch + 1, (ch + 1) & 1);
            asm volatile("cp.async.wait_group 1;" ::: "memory");
        } else {
            asm volatile("cp.async.wait_group 0;" ::: "memory");
        }
        __syncthreads();
        uint32_t sA = sb + (ch & 1) * 49152;
#pragma unroll
        for (int kk = 0; kk < 4; kk++) {
            uint32_t a[2][4];
#pragma unroll
            for (int mt = 0; mt < 2; mt++) {
                int r = wm*32 + mt*16 + (lane & 7) + ((lane >> 3) & 1) * 8;
                int cch = kk*2 + (lane >> 4);
                ldsm4(a[mt], sA + r*128 + ((cch ^ (r & 7)) << 4));
            }
            uint32_t bh[8][2], bl[8][2];
#pragma unroll
            for (int np = 0; np < 4; np++) {
                int r = wn*64 + np*16 + (lane & 7) + ((lane >> 4) & 1) * 8;
                int cch = kk*2 + ((lane >> 3) & 1);
                uint32_t off = r*128 + ((cch ^ (r & 7)) << 4);
                uint32_t d[4];
                ldsm4(d, sA + 16384 + off);
                bh[2*np][0]=d[0]; bh[2*np][1]=d[1];
                bh[2*np+1][0]=d[2]; bh[2*np+1][1]=d[3];
                ldsm4(d, sA + 32768 + off);
                bl[2*np][0]=d[0]; bl[2*np][1]=d[1];
                bl[2*np+1][0]=d[2]; bl[2*np+1][1]=d[3];
            }
#pragma unroll
            for (int mt = 0; mt < 2; mt++)
#pragma unroll
                for (int nt = 0; nt < 8; nt++) {
                    mma_h(acc[mt][nt], a[mt], bh[nt]);
                    mma_h(acc[mt][nt], a[mt], bl[nt]);
                }
        }
        __syncthreads();
    }

    int b_ = m0 >> 11;
    int ncol0 = n0 + wn*64;
    int h = ncol0 >> 6;
    float wv[8][2];
#pragma unroll
    for (int nt = 0; nt < 8; nt++) {
        int hd = nt*8 + (lane & 3)*2;
        wv[nt][0] = qnw[hd]; wv[nt][1] = qnw[hd + 1];
    }
#pragma unroll
    for (int mt = 0; mt < 2; mt++) {
#pragma unroll
        for (int half = 0; half < 2; half++) {
            int mrow = m0 + wm*32 + mt*16 + (lane >> 2) + half*8;
            int s = mrow & 2047;
            size_t rb = (((size_t)(b_*Hv + h))*Sv + s)*64;
            float ss = 0.f;
#pragma unroll
            for (int nt = 0; nt < 8; nt++) {
                float v0 = acc[mt][nt][half*2], v1 = acc[mt][nt][half*2+1];
                ss += v0*v0 + v1*v1;
            }
            ss += __shfl_xor_sync(0xffffffffu, ss, 1);
            ss += __shfl_xor_sync(0xffffffffu, ss, 2);
            float rinv = rsqrtf(ss / 64.f + 1e-6f);
#pragma unroll
            for (int nt = 0; nt < 8; nt++) {
                int hd = nt*8 + (lane & 3)*2;
                float v0 = acc[mt][nt][half*2]   * wv[nt][0] * rinv;
                float v1 = acc[mt][nt][half*2+1] * wv[nt][1] * rinv;
                *(float2*)&qout[rb + hd] = make_float2(v0, v1);
                *(__half2*)&qh[rb + hd] = __floats2half2_rn(v0, v1);
            }
        }
    }
#undef LOAD_Q
}

// ======== MLP GEMM 1: C[MT,256] = A[MT,64] @ B[256,64]^T (B K-major) ========
// MODE 0: store fwd -> o1 = pre, o2 = gelu(pre).
// MODE 1: dh0       -> o1 = acc * gelu'(o2=pre0).
// MODE 2: retrieve  -> B hi/lo 2-term; o1 = gelu single fp16.
template <int MODE>
__global__ void __launch_bounds__(256)
k_mlp0(const f16* __restrict__ A, const f16* __restrict__ Bhi,
       const f16* __restrict__ Blo, long long ws,
       f16* __restrict__ o1, f16* __restrict__ o2) {
    extern __shared__ char sm[];
    uint32_t sb = smem_u32(sm);
    constexpr uint32_t SB = 8192u;
    int tid = threadIdx.x, wid = tid >> 5, lane = tid & 31;
    int wm = wid >> 2, wn = wid & 3;          // 2(M) x 4(N)
    int m0 = blockIdx.x * 64;
    int bh = m0 >> 11;

    {
        const f16* Ab = A + (size_t)m0 * 64;
#pragma unroll
        for (int i = 0; i < 2; i++) {
            int idx = i*256 + tid; int r = idx >> 3, g = idx & 7;
            cp16(sb + r*128 + ((g ^ (r & 7)) << 4), Ab + r*64 + g*8);
        }
        const f16* Bb = Bhi + (size_t)bh * ws;
#pragma unroll
        for (int i = 0; i < 8; i++) {
            int idx = i*256 + tid; int r = idx >> 3, g = idx & 7;
            cp16(sb + SB + r*128 + ((g ^ (r & 7)) << 4), Bb + r*64 + g*8);
        }
        if (MODE == 2) {
            const f16* B2 = Blo + (size_t)bh * ws;
#pragma unroll
            for (int i = 0; i < 8; i++) {
                int idx = i*256 + tid; int r = idx >> 3, g = idx & 7;
                cp16(sb + SB + 32768 + r*128 + ((g ^ (r & 7)) << 4), B2 + r*64 + g*8);
            }
        }
    }
    asm volatile("cp.async.commit_group;\ncp.async.wait_group 0;" ::: "memory");
    __syncthreads();

    float acc[2][8][4];
#pragma unroll
    for (int mt = 0; mt < 2; mt++)
#pragma unroll
        for (int nt = 0; nt < 8; nt++)
#pragma unroll
            for (int e = 0; e < 4; e++) acc[mt][nt][e] = 0.f;

#pragma unroll
    for (int kk = 0; kk < 4; kk++) {
        uint32_t a[2][4];
#pragma unroll
        for (int mt = 0; mt < 2; mt++) {
            int r = wm*32 + mt*16 + (lane & 7) + ((lane >> 3) & 1) * 8;
            int cch = kk*2 + (lane >> 4);
            ldsm4(a[mt], sb + r*128 + ((cch ^ (r & 7)) << 4));
        }
        uint32_t bh_r[8][2], bl_r[8][2];
#pragma unroll
        for (int np = 0; np < 4; np++) {
            int r = wn*64 + np*16 + (lane & 7) + ((lane >> 4) & 1) * 8;
            int cch = kk*2 + ((lane >> 3) & 1);
            uint32_t off = r*128 + ((cch ^ (r & 7)) << 4);
            uint32_t d[4];
            ldsm4(d, sb + SB + off);
            bh_r[2*np][0]=d[0]; bh_r[2*np][1]=d[1];
            bh_r[2*np+1][0]=d[2]; bh_r[2*np+1][1]=d[3];
            if (MODE == 2) {
                ldsm4(d, sb + SB + 32768 + off);
                bl_r[2*np][0]=d[0]; bl_r[2*np][1]=d[1];
                bl_r[2*np+1][0]=d[2]; bl_r[2*np+1][1]=d[3];
            }
        }
#pragma unroll
        for (int mt = 0; mt < 2; mt++)
#pragma unroll
            for (int nt = 0; nt < 8; nt++) {
                mma_h(acc[mt][nt], a[mt], bh_r[nt]);
                if (MODE == 2) mma_h(acc[mt][nt], a[mt], bl_r[nt]);
            }
    }

#pragma unroll
    for (int mt = 0; mt < 2; mt++) {
        int mrow = m0 + wm*32 + mt*16 + (lane >> 2);
#pragma unroll
        for (int nt = 0; nt < 8; nt++) {
            int c = wn*64 + nt*8 + (lane & 3) * 2;
#pragma unroll
            for (int half = 0; half < 2; half++) {
                size_t off = (size_t)(mrow + half*8) * 256 + c;
                float v0 = acc[mt][nt][half*2], v1 = acc[mt][nt][half*2 + 1];
                if (MODE == 0) {
                    *(__half2*)&o1[off] = __floats2half2_rn(v0, v1);
                    *(__half2*)&o2[off] = __floats2half2_rn(geluf(v0), geluf(v1));
                } else if (MODE == 1) {
                    __half2 p2 = *(const __half2*)&o2[off];
                    float2 pf = __half22float2(p2);
                    *(__half2*)&o1[off] =
                        __floats2half2_rn(v0 * gelugrad(pf.x), v1 * gelugrad(pf.y));
                } else {
                    *(__half2*)&o1[off] = __floats2half2_rn(geluf(v0), geluf(v1));
                }
            }
        }
    }
}

// ======== MLP GEMM 2: C[MT,64] fp32 = A[MT,256] @ B[64,256]^T ==============
// MODE 0: store (B single). MODE 1: retrieve (B hi/lo 2-term).
template <int MODE>
__global__ void __launch_bounds__(256)
k_mlp1(const f16* __restrict__ A, const f16* __restrict__ Bhi,
       const f16* __restrict__ Blo, long long ws, float* __restrict__ Cout) {
    extern __shared__ char sm[];
    uint32_t sb = smem_u32(sm);
    constexpr uint32_t SB = 32768u;
    constexpr uint32_t ASTRIDE = 16384u;
    int tid = threadIdx.x, wid = tid >> 5, lane = tid & 31;
    int wm = wid >> 1, wn = wid & 1;          // 4(M) x 2(N)
    int m0 = blockIdx.x * 128;
    int bh = m0 >> 11;

    {   // B: [64][256] all-K resident
        const f16* Bb = Bhi + (size_t)bh * ws;
#pragma unroll
        for (int i = 0; i < 8; i++) {
            int idx = i*256 + tid; int r = idx >> 5, g = idx & 31;
            cp16(sb + SB + r*512 + ((g ^ (r & 7)) << 4), Bb + r*256 + g*8);
        }
        if (MODE == 1) {
            const f16* B2 = Blo + (size_t)bh * ws;
#pragma unroll
            for (int i = 0; i < 8; i++) {
                int idx = i*256 + tid; int r = idx >> 5, g = idx & 31;
                cp16(sb + SB + 32768 + r*512 + ((g ^ (r & 7)) << 4), B2 + r*256 + g*8);
            }
        }
    }
#define LA(CH, ST) do {                                                        \
    uint32_t _a = sb + (ST) * ASTRIDE;                                         \
    _Pragma("unroll")                                                          \
    for (int i = 0; i < 4; i++) {                                              \
        int idx = i*256 + tid; int r = idx >> 3, g = idx & 7;                  \
        cp16(_a + r*128 + ((g ^ (r & 7)) << 4),                                \
             A + (size_t)(m0 + r)*256 + (CH)*64 + g*8);                        \
    }                                                                          \
    asm volatile("cp.async.commit_group;" ::: "memory");                       \
} while (0)

    LA(0, 0);
    float acc[2][4][4];
#pragma unroll
    for (int mt = 0; mt < 2; mt++)
#pragma unroll
        for (int nt = 0; nt < 4; nt++)
#pragma unroll
            for (int e = 0; e < 4; e++) acc[mt][nt][e] = 0.f;

    for (int ch = 0; ch < 4; ch++) {
        if (ch < 3) {
            LA(ch + 1, (ch + 1) & 1);
            asm volatile("cp.async.wait_group 1;" ::: "memory");
        } else {
            asm volatile("cp.async.wait_group 0;" ::: "memory");
        }
        __syncthreads();
        uint32_t sA = sb + (ch & 1) * ASTRIDE;
#pragma unroll
        for (int kk = 0; kk < 4; kk++) {
            uint32_t a[2][4];
#pragma unroll
            for (int mt = 0; mt < 2; mt++) {
                int r = wm*32 + mt*16 + (lane & 7) + ((lane >> 3) & 1) * 8;
                int cch = kk*2 + (lane >> 4);
                ldsm4(a[mt], sA + r*128 + ((cch ^ (r & 7)) << 4));
            }
            uint32_t bh_r[4][2], bl_r[4][2];
#pragma unroll
            for (int np = 0; np < 2; np++) {
                int r = wn*32 + np*16 + (lane & 7) + ((lane >> 4) & 1) * 8;
                int kg = ch*8 + kk*2 + ((lane >> 3) & 1);
                uint32_t off = r*512 + ((kg ^ (r & 7)) << 4);
                uint32_t d[4];
                ldsm4(d, sb + SB + off);
                bh_r[2*np][0]=d[0]; bh_r[2*np][1]=d[1];
                bh_r[2*np+1][0]=d[2]; bh_r[2*np+1][1]=d[3];
                if (MODE == 1) {
                    ldsm4(d, sb + SB + 32768 + off);
                    bl_r[2*np][0]=d[0]; bl_r[2*np][1]=d[1];
                    bl_r[2*np+1][0]=d[2]; bl_r[2*np+1][1]=d[3];
                }
            }
#pragma unroll
            for (int mt = 0; mt < 2; mt++)
#pragma unroll
                for (int nt = 0; nt < 4; nt++) {
                    mma_h(acc[mt][nt], a[mt], bh_r[nt]);
                    if (MODE == 1) mma_h(acc[mt][nt], a[mt], bl_r[nt]);
                }
        }
        __syncthreads();
    }
#pragma unroll
    for (int mt = 0; mt < 2; mt++) {
        int mrow = m0 + wm*32 + mt*16 + (lane >> 2);
#pragma unroll
        for (int nt = 0; nt < 4; nt++) {
            int c = wn*32 + nt*8 + (lane & 3) * 2;
            *(float2*)&Cout[(size_t)mrow*64 + c]     = make_float2(acc[mt][nt][0], acc[mt][nt][1]);
            *(float2*)&Cout[(size_t)(mrow+8)*64 + c] = make_float2(acc[mt][nt][2], acc[mt][nt][3]);
        }
    }
#undef LA
}

// ======== gradT ============================================================
template <int MI, int NO>
__global__ void __launch_bounds__(256)
k_gradmma(const f16* __restrict__ A, const f16* __restrict__ Bm,
          float* __restrict__ G) {
    __shared__ __align__(16) char sm[32768];
    uint32_t sb = smem_u32(sm);
    int tid = threadIdx.x, wid = tid >> 5, lane = tid & 31;
    int wm = wid >> 2, wn = wid & 3;
    int bh = blockIdx.z;
    int m0 = blockIdx.y * 64, n0 = blockIdx.x * 64;
    const f16* Ab = A  + ((size_t)bh * Sv) * MI + m0;
    const f16* Bb = Bm + ((size_t)bh * Sv) * NO + n0;

#define LG(ST, S0) do {                                                        \
    _Pragma("unroll")                                                          \
    for (int i = 0; i < 2; i++) {                                              \
        int idx = i*256 + tid; int r = idx >> 3, g = idx & 7;                  \
        cp16(sb + (ST)*8192 + r*128 + ((g ^ (r & 7)) << 4),                    \
             Ab + (size_t)((S0) + r)*MI + g*8);                                \
        cp16(sb + 16384 + (ST)*8192 + r*128 + ((g ^ (r & 7)) << 4),            \
             Bb + (size_t)((S0) + r)*NO + g*8);                                \
    }                                                                          \
    asm volatile("cp.async.commit_group;" ::: "memory");                       \
} while (0)

    LG(0, 0);
    float acc[2][2][4];
#pragma unroll
    for (int mt = 0; mt < 2; mt++)
#pragma unroll
        for (int nt = 0; nt < 2; nt++)
#pragma unroll
            for (int e = 0; e < 4; e++) acc[mt][nt][e] = 0.f;

    for (int st = 0; st < 32; st++) {
        if (st < 31) {
            LG((st + 1) & 1, (st + 1) * 64);
            asm volatile("cp.async.wait_group 1;" ::: "memory");
        } else {
            asm volatile("cp.async.wait_group 0;" ::: "memory");
        }
        __syncthreads();
        uint32_t sA = sb + (st & 1) * 8192;
        uint32_t sB = sb + 16384 + (st & 1) * 8192;
#pragma unroll
        for (int kk = 0; kk < 4; kk++) {
            uint32_t aT[2][4];
#pragma unroll
            for (int mt = 0; mt < 2; mt++) {
                int row = kk*16 + (lane & 7) + ((lane >> 4) & 1) * 8;
                int cg = wm*4 + mt*2 + ((lane >> 3) & 1);
                ldsm4t(aT[mt], sA + row*128 + ((cg ^ (row & 7)) << 4));
            }
            int row = kk*16 + (lane & 7) + ((lane >> 3) & 1) * 8;
            int cg = wn*2 + (lane >> 4);
            uint32_t d[4];
            ldsm4t(d, sB + row*128 + ((cg ^ (row & 7)) << 4));
            uint32_t bT[2][2] = {{d[0], d[1]}, {d[2], d[3]}};
#pragma unroll
            for (int mt = 0; mt < 2; mt++)
#pragma unroll
                for (int nt = 0; nt < 2; nt++)
                    mma_h(acc[mt][nt], aT[mt], bT[nt]);
        }
        __syncthreads();
    }
#pragma unroll
    for (int mt = 0; mt < 2; mt++) {
        int m = m0 + wm*32 + mt*16 + (lane >> 2);
#pragma unroll
        for (int nt = 0; nt < 2; nt++) {
            int n = n0 + wn*16 + nt*8 + (lane & 3) * 2;
            *(float2*)&G[((size_t)bh*MI + m)*NO + n]     = make_float2(acc[mt][nt][0], acc[mt][nt][1]);
            *(float2*)&G[((size_t)bh*MI + m + 8)*NO + n] = make_float2(acc[mt][nt][2], acc[mt][nt][3]);
        }
    }
#undef LG
}

// ---------- fused pf_rmsnorm fwd+bwd for the store loss gradient ------------
__global__ void k_dh(const f16* __restrict__ keysb, f16* __restrict__ dhb) {
    int r = blockIdx.x * 8 + (threadIdx.x >> 5);
    int lane = threadIdx.x & 31;
    size_t base = (size_t)r * 64;
    float h0 = g_pre1[base + lane], h1 = g_pre1[base + lane + 32];
    float ss = h0*h0 + h1*h1;
#pragma unroll
    for (int o = 16; o > 0; o >>= 1) ss += __shfl_xor_sync(0xffffffffu, ss, o);
    float rms = sqrtf(ss / 64.f + 1e-8f);
    float hn0 = h0 / rms, hn1 = h1 / rms;
    float t = g_theta[r];
    float k0 = __half2float(keysb[base + lane]);
    float k1 = __half2float(keysb[base + lane + 32]);
    float dp0 = 2.f * t * ((hn0 + k0) - g_values[base + lane]);
    float dp1 = 2.f * t * ((hn1 + k1) - g_values[base + lane + 32]);
    float dy = dp0*hn0 + dp1*hn1;
#pragma unroll
    for (int o = 16; o > 0; o >>= 1) dy += __shfl_xor_sync(0xffffffffu, dy, o);
    dhb[base + lane]      = __float2half((dp0 - hn0 * dy / 64.f) / rms);
    dhb[base + lane + 32] = __float2half((dp1 - hn1 * dy / 64.f) / rms);
}

// ---------------- gates: alpha, theta (reads fp16 xn) -----------------------
__global__ void __launch_bounds__(256)
k_gates(const f16* __restrict__ xn,
        const float* __restrict__ aw, const float* __restrict__ ab,
        const float* __restrict__ tw, const float* __restrict__ tb) {
    __shared__ float Xs[64][128];
    __shared__ float Ws[64][32];
    int m0 = blockIdx.x * 128;
    int tid = threadIdx.x;
    int rg = tid >> 3, cg = tid & 7;
    float acc[4][4] = {};
    for (int k0 = 0; k0 < 1024; k0 += 64) {
#pragma unroll
        for (int i = 0; i < 4; i++) {
            int idx = tid + i*256;
            int r = idx >> 3, c8 = idx & 7;
            size_t ga = (size_t)(m0 + r)*1024 + k0 + c8*8;
            uint4 vh = *(const uint4*)&xn[ga];
            __half2 h2[4];
            *(uint4*)h2 = vh;
#pragma unroll
            for (int j = 0; j < 4; j++) {
                float2 fh = __half22float2(h2[j]);
                Xs[c8*8 + 2*j][r]     = fh.x;
                Xs[c8*8 + 2*j + 1][r] = fh.y;
            }
        }
#pragma unroll
        for (int i = 0; i < 2; i++) {
            int idx = tid + i*256;
            int r = idx >> 3, c4 = idx & 7;
            const float* src = (c4 < 4) ? (aw + (size_t)(k0 + r)*16 + c4*4)
                                        : (tw + (size_t)(k0 + r)*16 + (c4 - 4)*4);
            *(float4*)&Ws[r][c4*4] = *(const float4*)src;
        }
        __syncthreads();
#pragma unroll
        for (int k = 0; k < 64; k++) {
            float ra[4], rb[4];
#pragma unroll
            for (int i = 0; i < 4; i++) ra[i] = Xs[k][rg*4 + i];
#pragma unroll
            for (int j = 0; j < 4; j++) rb[j] = Ws[k][cg*4 + j];
#pragma unroll
            for (int i = 0; i < 4; i++)
#pragma unroll
                for (int j = 0; j < 4; j++) acc[i][j] += ra[i] * rb[j];
        }
        __syncthreads();
    }
#pragma unroll
    for (int i = 0; i < 4; i++) {
        int m = m0 + rg*4 + i;
        int b = m >> 11, s = m & 2047;
#pragma unroll
        for (int j = 0; j < 4; j++) {
            int c = cg*4 + j;
            int h = c & 15;
            size_t off = ((size_t)(b*Hv + h))*Sv + s;
            if (c < 16) g_alpha[off] = 1.f / (1.f + expf(-(acc[i][j] + ab[h])));
            else        g_theta[off] = 0.01f / (1.f + expf(-(acc[i][j] + tb[h])));
        }
    }
}

// ---------------- per-bh reductions -----------------------------------------
__global__ void k_amean() {
    int bh = blockIdx.x; int tid = threadIdx.x;
    float s = 0.f;
    for (int i = tid; i < Sv; i += 256) s += g_alpha[(size_t)bh*Sv + i];
#pragma unroll
    for (int o = 16; o > 0; o >>= 1) s += __shfl_xor_sync(0xffffffffu, s, o);
    __shared__ float red[8];
    if ((tid & 31) == 0) red[tid >> 5] = s;
    __syncthreads();
    if (tid == 0) {
        float t = 0.f;
#pragma unroll
        for (int i = 0; i < 8; i++) t += red[i];
        g_amean[bh] = t / (float)Sv;
    }
}

__global__ void k_clip() {
    int bh = blockIdx.x; int tid = threadIdx.x;
    const float* a = g_g0 + (size_t)bh * 16384;
    const float* b = g_g1 + (size_t)bh * 16384;
    float s = 0.f;
    for (int i = tid; i < 16384; i += 256) {
        float v = a[i]; s += v*v;
        v = b[i]; s += v*v;
    }
#pragma unroll
    for (int o = 16; o > 0; o >>= 1) s += __shfl_xor_sync(0xffffffffu, s, o);
    __shared__ float red[8];
    if ((tid & 31) == 0) red[tid >> 5] = s;
    __syncthreads();
    if (tid == 0) {
        float t = 0.f;
#pragma unroll
        for (int i = 0; i < 8; i++) t += red[i];
        float c = 10.f / (sqrtf(t) + 1e-6f);
        g_coef[bh] = c < 1.f ? c : 1.f;
    }
}

// ---------------- weight prep + update --------------------------------------
__global__ void k_tr(const float* __restrict__ src, float* __restrict__ dstF,
                     f16* __restrict__ dstB, int R, int C) {
    int idx = blockIdx.x * 256 + threadIdx.x;
    if (idx >= R*C) return;
    int c = idx / R, r = idx % R;
    float v = src[r*C + c];
    dstF[idx] = v;
    dstB[idx] = __float2half(v);
}
__global__ void k_cpb(const float* __restrict__ s, f16* __restrict__ d, int n) {
    int idx = blockIdx.x * 256 + threadIdx.x;
    if (idx < n) d[idx] = __float2half(s[idx]);
}
__global__ void k_newwT(const float* __restrict__ WT, const float* __restrict__ gT,
                        f16* __restrict__ ohi, f16* __restrict__ olo) {
    size_t idx = (size_t)blockIdx.x * 256 + threadIdx.x;
    int bh = (int)(idx >> 14); int e = (int)(idx & 16383);
    float w = WT[e];
    float nw = (1.f - g_amean[bh]) * w - g_coef[bh] * gT[idx];
    if (!isfinite(nw)) nw = w;
    f16 h = __float2half(nw);
    ohi[idx] = h;
    olo[idx] = __float2half(nw - __half2float(h));
}

// ---------------- retrieve epilogue -----------------------------------------
__global__ void k_final(float* __restrict__ out) {
    int r = blockIdx.x * 8 + (threadIdx.x >> 5);
    int lane = threadIdx.x & 31;
    size_t base = (size_t)r * 64;
    float h0 = g_pre1[base + lane], h1 = g_pre1[base + lane + 32];
    if (!isfinite(h0)) h0 = 0.f;
    if (!isfinite(h1)) h1 = 0.f;
    float ss = h0*h0 + h1*h1;
#pragma unroll
    for (int o = 16; o > 0; o >>= 1) ss += __shfl_xor_sync(0xffffffffu, ss, o);
    float rms = sqrtf(ss / 64.f + 1e-8f);
    float o0 = h0 / rms + g_q[base + lane];
    float o1 = h1 / rms + g_q[base + lane + 32];
    int bh = r >> 11, s = r & 2047;
    int b = bh >> 4, hh = bh & 15;
    size_t ob = ((size_t)(b*Sv + s))*Dv + hh*64;
    out[ob + lane]      = o0;
    out[ob + lane + 32] = o1;
}

// ============================================================================
extern "C" void kernel_launch(void* const* d_in, const int* in_sizes, int n_in,
                              void* d_out, int out_size) {
    (void)in_sizes; (void)n_in; (void)out_size;
    const float* x   = (const float*)d_in[0];
    const float* W_K = (const float*)d_in[1];
    const float* W_V = (const float*)d_in[2];
    const float* W_Q = (const float*)d_in[3];
    const float* mW0 = (const float*)d_in[4];
    const float* mW1 = (const float*)d_in[5];
    const float* knw = (const float*)d_in[6];
    const float* qnw = (const float*)d_in[7];
    const float* snw = (const float*)d_in[8];
    const float* rnw = (const float*)d_in[9];
    const float* aw  = (const float*)d_in[10];
    const float* ab  = (const float*)d_in[11];
    const float* tw  = (const float*)d_in[12];
    const float* tb  = (const float*)d_in[13];
    float* out = (float*)d_out;

    f16 *xnh, *wkv, *wqhi, *wqlo, *keysb, *qh, *dhb, *mW0Tb, *mW1Tb, *mW1b;
    f16 *nW0Thi, *nW0Tlo, *nW1Thi, *nW1Tlo;
    float *values, *q, *pre1, *g0p, *g1p, *mW0T, *mW1T;
    char* pool;
    cudaGetSymbolAddress((void**)&xnh,    g_xnh);
    cudaGetSymbolAddress((void**)&wkv,    g_wkv);
    cudaGetSymbolAddress((void**)&wqhi,   g_wqhi);
    cudaGetSymbolAddress((void**)&wqlo,   g_wqlo);
    cudaGetSymbolAddress((void**)&values, g_values);
    cudaGetSymbolAddress((void**)&q,      g_q);
    cudaGetSymbolAddress((void**)&pre1,   g_pre1);
    cudaGetSymbolAddress((void**)&keysb,  g_keysb);
    cudaGetSymbolAddress((void**)&qh,     g_qh);
    cudaGetSymbolAddress((void**)&dhb,    g_dhb);
    cudaGetSymbolAddress((void**)&pool,   g_pool);
    cudaGetSymbolAddress((void**)&g0p,    g_g0);
    cudaGetSymbolAddress((void**)&g1p,    g_g1);
    cudaGetSymbolAddress((void**)&mW0T,   g_mW0T);
    cudaGetSymbolAddress((void**)&mW1T,   g_mW1T);
    cudaGetSymbolAddress((void**)&mW0Tb,  g_mW0Tb);
    cudaGetSymbolAddress((void**)&mW1Tb,  g_mW1Tb);
    cudaGetSymbolAddress((void**)&mW1b,   g_mW1b);
    cudaGetSymbolAddress((void**)&nW0Thi, g_nW0Thi);
    cudaGetSymbolAddress((void**)&nW0Tlo, g_nW0Tlo);
    cudaGetSymbolAddress((void**)&nW1Thi, g_nW1Thi);
    cudaGetSymbolAddress((void**)&nW1Tlo, g_nW1Tlo);

    f16* pre0h = (f16*)(pool);
    f16* h1h   = (f16*)(pool + 134217728);
    f16* dh0h  = (f16*)(pool + 268435456);
    f16* h1rh  = (f16*)(pool);                // aliases pre0h (dead by then)

    cudaFuncSetAttribute(k_gemm_kv, cudaFuncAttributeMaxDynamicSharedMemorySize, KV_SMEM);
    cudaFuncSetAttribute(k_gemm_q,  cudaFuncAttributeMaxDynamicSharedMemorySize, Q_SMEM);
    cudaFuncSetAttribute(k_mlp0<0>, cudaFuncAttributeMaxDynamicSharedMemorySize, 40960);
    cudaFuncSetAttribute(k_mlp0<1>, cudaFuncAttributeMaxDynamicSharedMemorySize, 40960);
    cudaFuncSetAttribute(k_mlp0<2>, cudaFuncAttributeMaxDynamicSharedMemorySize, 73728);
    cudaFuncSetAttribute(k_mlp1<0>, cudaFuncAttributeMaxDynamicSharedMemorySize, 65536);
    cudaFuncSetAttribute(k_mlp1<1>, cudaFuncAttributeMaxDynamicSharedMemorySize, 98304);

    dim3 gws(32, 32), bws(32, 8);

    // ---- weight prep (independent) ----
    k_tr<<<64, 256>>>(mW0, mW0T, mW0Tb, HDv, HIDv);   // -> [256][64]
    k_tr<<<64, 256>>>(mW1, mW1T, mW1Tb, HIDv, HDv);   // -> [64][256]
    k_cpb<<<64, 256>>>(mW1, mW1b, HIDv*HDv);

    // ---- store path ----
    k_rmsnorm16<<<Mv, 256>>>(x, snw, xnh);
    k_wt16<<<gws, bws>>>(W_K, wkv);
    k_wt16<<<gws, bws>>>(W_V, wkv + (size_t)Dv*Dv);
    k_gemm_kv<<<dim3(16, 128), 256, KV_SMEM>>>(xnh, wkv, keysb, values, knw);
    k_gates<<<Mv/128, 256>>>(xnh, aw, ab, tw, tb);
    k_amean<<<BHv, 256>>>();

    k_mlp0<0><<<MTv/64, 256, 40960>>>(keysb, mW0Tb, nullptr, 0, pre0h, h1h);
    k_mlp1<0><<<MTv/128, 256, 65536>>>(h1h, mW1Tb, nullptr, 0, pre1);
    k_dh<<<MTv/8, 256>>>(keysb, dhb);
    // dh0 written in place over pre0h (same-thread same-offset read/write)
    k_mlp0<1><<<MTv/64, 256, 40960>>>(dhb, mW1b, nullptr, 0, dh0h, pre0h);

    k_gradmma<HDv, HIDv><<<dim3(4, 1, BHv), 256>>>(dhb, h1h, g1p);     // g1^T [64][256]
    k_gradmma<HIDv, HDv><<<dim3(1, 4, BHv), 256>>>(dh0h, keysb, g0p);  // g0^T [256][64]
    k_clip<<<BHv, 256>>>();
    k_newwT<<<(BHv*16384)/256, 256>>>(mW0T, g0p, nW0Thi, nW0Tlo);
    k_newwT<<<(BHv*16384)/256, 256>>>(mW1T, g1p, nW1Thi, nW1Tlo);

    // ---- retrieve path ----
    k_rmsnorm16<<<Mv, 256>>>(x, rnw, xnh);
    k_wt2<<<gws, bws>>>(W_Q, wqhi, wqlo);
    k_gemm_q<<<dim3(8, 128), 256, Q_SMEM>>>(xnh, wqhi, wqlo, q, qh, qnw);
    k_mlp0<2><<<MTv/64, 256, 73728>>>(qh, nW0Thi, nW0Tlo,
                                      (long long)HIDv*HDv, h1rh, nullptr);
    k_mlp1<1><<<MTv/128, 256, 98304>>>(h1rh, nW1Thi, nW1Tlo,
                                       (long long)HDv*HIDv, pre1);
    k_final<<<MTv/8, 256>>>(out);
}

// round 14
// speedup vs baseline: 2.1087x; 1.0414x over previous
#include <cuda_runtime.h>
#include <cuda_bf16.h>
#include <cuda_fp16.h>
#include <math.h>
#include <stdint.h>

// Problem constants
#define Bv   8
#define Sv   2048
#define Dv   1024
#define Hv   16
#define HDv  64
#define HIDv 256
#define BHv  128               // B*H
#define Mv   (Bv*Sv)           // 16384 rows of x
#define MTv  (BHv*Sv)          // 262144 rows per-head

typedef __half f16;

// ------------------------- scratch (device globals) -------------------------
__device__ f16  g_xnh[Mv*Dv];         // 32 MB
__device__ f16  g_wkv[2*Dv*Dv];       // 4 MB (W_K^T | W_V^T)
__device__ f16  g_wqhi[Dv*Dv];        // 2 MB
__device__ f16  g_wqlo[Dv*Dv];        // 2 MB
__device__ f16  g_values[MTv*HDv];    // 32 MB (fp16)
__device__ float g_q[MTv*HDv];        // 64 MB (normed q, fp32 residual)
__device__ f16  g_keysb[MTv*HDv];     // 32 MB
__device__ f16  g_qh[MTv*HDv];        // 32 MB
__device__ f16  g_dhb[MTv*HDv];       // 32 MB
// pooled scratch: pre0h@0, h1h@128M, dh0h@256M; retrieve: h1rh@0
__device__ __align__(256) char g_pool[402653184];   // 384 MB
__device__ float g_alpha[BHv*Sv];
__device__ float g_theta[BHv*Sv];
__device__ float g_amean[BHv];
__device__ float g_coef[BHv];
__device__ float g_g0[BHv*HIDv*HDv];
__device__ float g_g1[BHv*HDv*HIDv];
__device__ float g_mW0T[HIDv*HDv];    __device__ f16 g_mW0Tb[HIDv*HDv];
__device__ float g_mW1T[HDv*HIDv];    __device__ f16 g_mW1Tb[HDv*HIDv];
__device__ f16 g_mW1b[HIDv*HDv];
__device__ f16 g_nW0Thi[BHv*HIDv*HDv], g_nW0Tlo[BHv*HIDv*HDv];
__device__ f16 g_nW1Thi[BHv*HDv*HIDv], g_nW1Tlo[BHv*HDv*HIDv];

// ========================= mma.sync helpers =================================
__device__ __forceinline__ uint32_t smem_u32(const void* p) {
    uint32_t a;
    asm("{ .reg .u64 t; cvta.to.shared.u64 t, %1; cvt.u32.u64 %0, t; }"
        : "=r"(a) : "l"(p));
    return a;
}
__device__ __forceinline__ void ldsm4(uint32_t* d, uint32_t addr) {
    asm volatile("ldmatrix.sync.aligned.m8n8.x4.shared.b16 {%0,%1,%2,%3}, [%4];"
                 : "=r"(d[0]), "=r"(d[1]), "=r"(d[2]), "=r"(d[3]) : "r"(addr));
}
__device__ __forceinline__ void ldsm4t(uint32_t* d, uint32_t addr) {
    asm volatile("ldmatrix.sync.aligned.m8n8.x4.trans.shared.b16 {%0,%1,%2,%3}, [%4];"
                 : "=r"(d[0]), "=r"(d[1]), "=r"(d[2]), "=r"(d[3]) : "r"(addr));
}
__device__ __forceinline__ void mma_h(float* c, const uint32_t* a, const uint32_t* b) {
    asm volatile("mma.sync.aligned.m16n8k16.row.col.f32.f16.f16.f32 "
                 "{%0,%1,%2,%3}, {%4,%5,%6,%7}, {%8,%9}, {%0,%1,%2,%3};"
                 : "+f"(c[0]), "+f"(c[1]), "+f"(c[2]), "+f"(c[3])
                 : "r"(a[0]), "r"(a[1]), "r"(a[2]), "r"(a[3]), "r"(b[0]), "r"(b[1]));
}
__device__ __forceinline__ void cp16(uint32_t dst, const void* src) {
    asm volatile("cp.async.cg.shared.global [%0], [%1], 16;" :: "r"(dst), "l"(src) : "memory");
}
__device__ __forceinline__ float geluf(float v) {
    return 0.5f * v * (1.f + erff(v * 0.70710678118654752f));
}
__device__ __forceinline__ float gelugrad(float p) {
    float cdf = 0.5f * (1.f + erff(p * 0.70710678118654752f));
    float pdf = expf(-0.5f * p * p) * 0.3989422804014327f;
    return cdf + p * pdf;
}

// ---------------- rmsnorm over D=1024 rows, emit fp16 -----------------------
__global__ void k_rmsnorm16(const float* __restrict__ x, const float* __restrict__ w,
                            f16* __restrict__ o) {
    int row = blockIdx.x;
    const float* xr = x + (size_t)row * Dv;
    int tid = threadIdx.x;
    float v[4]; float ss = 0.f;
#pragma unroll
    for (int i = 0; i < 4; i++) { v[i] = xr[tid + i*256]; ss += v[i]*v[i]; }
#pragma unroll
    for (int o2 = 16; o2 > 0; o2 >>= 1) ss += __shfl_xor_sync(0xffffffffu, ss, o2);
    __shared__ float red[8];
    __shared__ float rinv;
    if ((tid & 31) == 0) red[tid >> 5] = ss;
    __syncthreads();
    if (tid == 0) {
        float t = 0.f;
#pragma unroll
        for (int i = 0; i < 8; i++) t += red[i];
        rinv = rsqrtf(t / (float)Dv + 1e-6f);
    }
    __syncthreads();
    float r = rinv;
#pragma unroll
    for (int i = 0; i < 4; i++)
        o[(size_t)row*Dv + tid + i*256] = __float2half(v[i] * w[tid + i*256] * r);
}

// ---------------- transpose weight -> fp16 (single) -------------------------
__global__ void k_wt16(const float* __restrict__ W, f16* __restrict__ T) {
    __shared__ float t[32][33];
    int k0 = blockIdx.y * 32, n0 = blockIdx.x * 32;
    int tx = threadIdx.x, ty = threadIdx.y;
#pragma unroll
    for (int r = 0; r < 4; r++)
        t[ty + r*8][tx] = W[(size_t)(k0 + ty + r*8)*Dv + n0 + tx];
    __syncthreads();
#pragma unroll
    for (int r = 0; r < 4; r++)
        T[(size_t)(n0 + ty + r*8)*Dv + k0 + tx] = __float2half(t[tx][ty + r*8]);
}

// ---------------- transpose weight -> fp16 hi/lo -----------------------------
__global__ void k_wt2(const float* __restrict__ W,
                      f16* __restrict__ Thi, f16* __restrict__ Tlo) {
    __shared__ float t[32][33];
    int k0 = blockIdx.y * 32, n0 = blockIdx.x * 32;
    int tx = threadIdx.x, ty = threadIdx.y;
#pragma unroll
    for (int r = 0; r < 4; r++)
        t[ty + r*8][tx] = W[(size_t)(k0 + ty + r*8)*Dv + n0 + tx];
    __syncthreads();
#pragma unroll
    for (int r = 0; r < 4; r++) {
        float v = t[tx][ty + r*8];
        f16 h = __float2half(v);
        size_t off = (size_t)(n0 + ty + r*8)*Dv + k0 + tx;
        Thi[off] = h;
        Tlo[off] = __float2half(v - __half2float(h));
    }
}

// ===== fused K+V GEMM: (16384x1024)@(1024x2048) fp16 single-pass ============
#define KV_SMEM (2*32768)
__global__ void __launch_bounds__(256)
k_gemm_kv(const f16* __restrict__ A, const f16* __restrict__ Bw,
          f16* __restrict__ keysb, f16* __restrict__ valh,
          const float* __restrict__ knw) {
    extern __shared__ char smem[];
    uint32_t sb = smem_u32(smem);
    int tid = threadIdx.x;
    int wid = tid >> 5, lane = tid & 31;
    int wm = wid >> 1, wn = wid & 1;
    int m0 = blockIdx.y * 128, n0 = blockIdx.x * 128;

#define LOAD_KV(CH, ST) do {                                                   \
    int _k0 = (CH) * 64;                                                       \
    uint32_t _sb = sb + (ST) * 32768;                                          \
    _Pragma("unroll")                                                          \
    for (int i = 0; i < 8; i++) {                                              \
        int idx = i * 256 + tid;                                               \
        int layer = idx >> 10, rem = idx & 1023;                               \
        int r = rem >> 3, g = rem & 7;                                         \
        const f16* src = layer ? Bw + (size_t)(n0 + r) * Dv + _k0 + g * 8      \
                               : A  + (size_t)(m0 + r) * Dv + _k0 + g * 8;     \
        cp16(_sb + layer * 16384 + r * 128 + ((g ^ (r & 7)) << 4), src);       \
    }                                                                          \
    asm volatile("cp.async.commit_group;" ::: "memory");                       \
} while (0)

    LOAD_KV(0, 0);
    float acc[2][8][4];
#pragma unroll
    for (int mt = 0; mt < 2; mt++)
#pragma unroll
        for (int nt = 0; nt < 8; nt++)
#pragma unroll
            for (int e = 0; e < 4; e++) acc[mt][nt][e] = 0.f;

    for (int ch = 0; ch < 16; ch++) {
        if (ch < 15) {
            LOAD_KV(ch + 1, (ch + 1) & 1);
            asm volatile("cp.async.wait_group 1;" ::: "memory");
        } else {
            asm volatile("cp.async.wait_group 0;" ::: "memory");
        }
        __syncthreads();
        uint32_t sA = sb + (ch & 1) * 32768;
        uint32_t sB = sA + 16384;
#pragma unroll
        for (int kk = 0; kk < 4; kk++) {
            uint32_t a[2][4];
#pragma unroll
            for (int mt = 0; mt < 2; mt++) {
                int r = wm*32 + mt*16 + (lane & 7) + ((lane >> 3) & 1) * 8;
                int cch = kk*2 + (lane >> 4);
                ldsm4(a[mt], sA + r*128 + ((cch ^ (r & 7)) << 4));
            }
            uint32_t b[8][2];
#pragma unroll
            for (int np = 0; np < 4; np++) {
                int r = wn*64 + np*16 + (lane & 7) + ((lane >> 4) & 1) * 8;
                int cch = kk*2 + ((lane >> 3) & 1);
                uint32_t d[4];
                ldsm4(d, sB + r*128 + ((cch ^ (r & 7)) << 4));
                b[2*np][0]=d[0]; b[2*np][1]=d[1];
                b[2*np+1][0]=d[2]; b[2*np+1][1]=d[3];
            }
#pragma unroll
            for (int mt = 0; mt < 2; mt++)
#pragma unroll
                for (int nt = 0; nt < 8; nt++)
                    mma_h(acc[mt][nt], a[mt], b[nt]);
        }
        __syncthreads();
    }

    int b_ = m0 >> 11;
    int ncol0 = n0 + wn*64;
    bool isK = ncol0 < 1024;
    int h = (isK ? ncol0 : ncol0 - 1024) >> 6;
    float wv[8][2];
    if (isK) {
#pragma unroll
        for (int nt = 0; nt < 8; nt++) {
            int hd = nt*8 + (lane & 3)*2;
            wv[nt][0] = knw[hd]; wv[nt][1] = knw[hd + 1];
        }
    }
#pragma unroll
    for (int mt = 0; mt < 2; mt++) {
#pragma unroll
        for (int half = 0; half < 2; half++) {
            int mrow = m0 + wm*32 + mt*16 + (lane >> 2) + half*8;
            int s = mrow & 2047;
            size_t rb = (((size_t)(b_*Hv + h))*Sv + s)*64;
            if (isK) {
                float ss = 0.f;
#pragma unroll
                for (int nt = 0; nt < 8; nt++) {
                    float v0 = acc[mt][nt][half*2], v1 = acc[mt][nt][half*2+1];
                    ss += v0*v0 + v1*v1;
                }
                ss += __shfl_xor_sync(0xffffffffu, ss, 1);
                ss += __shfl_xor_sync(0xffffffffu, ss, 2);
                float rinv = rsqrtf(ss / 64.f + 1e-6f);
#pragma unroll
                for (int nt = 0; nt < 8; nt++) {
                    int hd = nt*8 + (lane & 3)*2;
                    float v0 = acc[mt][nt][half*2]   * wv[nt][0] * rinv;
                    float v1 = acc[mt][nt][half*2+1] * wv[nt][1] * rinv;
                    *(__half2*)&keysb[rb + hd] = __floats2half2_rn(v0, v1);
                }
            } else {
#pragma unroll
                for (int nt = 0; nt < 8; nt++) {
                    int hd = nt*8 + (lane & 3)*2;
                    *(__half2*)&valh[rb + hd] =
                        __floats2half2_rn(acc[mt][nt][half*2], acc[mt][nt][half*2+1]);
                }
            }
        }
    }
#undef LOAD_KV
}

// ===== Q GEMM: (16384x1024)@(1024x1024), 2-term fp16 ========================
#define Q_SMEM (2*49152)
__global__ void __launch_bounds__(256)
k_gemm_q(const f16* __restrict__ A, const f16* __restrict__ Bhi,
         const f16* __restrict__ Blo, float* __restrict__ qout,
         f16* __restrict__ qh, const float* __restrict__ qnw) {
    extern __shared__ char smem[];
    uint32_t sb = smem_u32(smem);
    int tid = threadIdx.x;
    int wid = tid >> 5, lane = tid & 31;
    int wm = wid >> 1, wn = wid & 1;
    int m0 = blockIdx.y * 128, n0 = blockIdx.x * 128;

    const f16* base_l[3] = { A + (size_t)m0 * Dv,
                             Bhi + (size_t)n0 * Dv, Blo + (size_t)n0 * Dv };
#define LOAD_Q(CH, ST) do {                                                    \
    int _k0 = (CH) * 64;                                                       \
    uint32_t _sb = sb + (ST) * 49152;                                          \
    _Pragma("unroll")                                                          \
    for (int i = 0; i < 12; i++) {                                             \
        int idx = i * 256 + tid;                                               \
        int layer = idx >> 10, rem = idx & 1023;                               \
        int r = rem >> 3, g = rem & 7;                                         \
        const f16* src = base_l[layer] + (size_t)r * Dv + _k0 + g * 8;         \
        cp16(_sb + layer * 16384 + r * 128 + ((g ^ (r & 7)) << 4), src);       \
    }                                                                          \
    asm volatile("cp.async.commit_group;" ::: "memory");                       \
} while (0)

    LOAD_Q(0, 0);
    float acc[2][8][4];
#pragma unroll
    for (int mt = 0; mt < 2; mt++)
#pragma unroll
        for (int nt = 0; nt < 8; nt++)
#pragma unroll
            for (int e = 0; e < 4; e++) acc[mt][nt][e] = 0.f;

    for (int ch = 0; ch < 16; ch++) {
        if (ch < 15) {
            LOAD_Q(ch + 1, (ch + 1) & 1);
            asm volatile("cp.async.wait_group 1;" ::: "memory");
        } else {
            asm volatile("cp.async.wait_group 0;" ::: "memory");
        }
        __syncthreads();
        uint32_t sA = sb + (ch & 1) * 49152;
#pragma unroll
        for (int kk = 0; kk < 4; kk++) {
            uint32_t a[2][4];
#pragma unroll
            for (int mt = 0; mt < 2; mt++) {
                int r = wm*32 + mt*16 + (lane & 7) + ((lane >> 3) & 1) * 8;
                int cch = kk*2 + (lane >> 4);
                ldsm4(a[mt], sA + r*128 + ((cch ^ (r & 7)) << 4));
            }
            uint32_t bh[8][2], bl[8][2];
#pragma unroll
            for (int np = 0; np < 4; np++) {
                int r = wn*64 + np*16 + (lane & 7) + ((lane >> 4) & 1) * 8;
                int cch = kk*2 + ((lane >> 3) & 1);
                uint32_t off = r*128 + ((cch ^ (r & 7)) << 4);
                uint32_t d[4];
                ldsm4(d, sA + 16384 + off);
                bh[2*np][0]=d[0]; bh[2*np][1]=d[1];
                bh[2*np+1][0]=d[2]; bh[2*np+1][1]=d[3];
                ldsm4(d, sA + 32768 + off);
                bl[2*np][0]=d[0]; bl[2*np][1]=d[1];
                bl[2*np+1][0]=d[2]; bl[2*np+1][1]=d[3];
            }
#pragma unroll
            for (int mt = 0; mt < 2; mt++)
#pragma unroll
                for (int nt = 0; nt < 8; nt++) {
                    mma_h(acc[mt][nt], a[mt], bh[nt]);
                    mma_h(acc[mt][nt], a[mt], bl[nt]);
                }
        }
        __syncthreads();
    }

    int b_ = m0 >> 11;
    int ncol0 = n0 + wn*64;
    int h = ncol0 >> 6;
    float wv[8][2];
#pragma unroll
    for (int nt = 0; nt < 8; nt++) {
        int hd = nt*8 + (lane & 3)*2;
        wv[nt][0] = qnw[hd]; wv[nt][1] = qnw[hd + 1];
    }
#pragma unroll
    for (int mt = 0; mt < 2; mt++) {
#pragma unroll
        for (int half = 0; half < 2; half++) {
            int mrow = m0 + wm*32 + mt*16 + (lane >> 2) + half*8;
            int s = mrow & 2047;
            size_t rb = (((size_t)(b_*Hv + h))*Sv + s)*64;
            float ss = 0.f;
#pragma unroll
            for (int nt = 0; nt < 8; nt++) {
                float v0 = acc[mt][nt][half*2], v1 = acc[mt][nt][half*2+1];
                ss += v0*v0 + v1*v1;
            }
            ss += __shfl_xor_sync(0xffffffffu, ss, 1);
            ss += __shfl_xor_sync(0xffffffffu, ss, 2);
            float rinv = rsqrtf(ss / 64.f + 1e-6f);
#pragma unroll
            for (int nt = 0; nt < 8; nt++) {
                int hd = nt*8 + (lane & 3)*2;
                float v0 = acc[mt][nt][half*2]   * wv[nt][0] * rinv;
                float v1 = acc[mt][nt][half*2+1] * wv[nt][1] * rinv;
                *(float2*)&qout[rb + hd] = make_float2(v0, v1);
                *(__half2*)&qh[rb + hd] = __floats2half2_rn(v0, v1);
            }
        }
    }
#undef LOAD_Q
}

// ======== MLP GEMM 1: C[MT,256] = A[MT,64] @ B[256,64]^T ====================
// MODE 0: store fwd -> o1 = pre, o2 = gelu(pre).
// MODE 1: dh0       -> o1 = acc * gelu'(o2=pre0).
// MODE 2: retrieve  -> B hi/lo 2-term; o1 = gelu single fp16.
template <int MODE>
__global__ void __launch_bounds__(256)
k_mlp0(const f16* __restrict__ A, const f16* __restrict__ Bhi,
       const f16* __restrict__ Blo, long long ws,
       f16* __restrict__ o1, f16* __restrict__ o2) {
    extern __shared__ char sm[];
    uint32_t sb = smem_u32(sm);
    constexpr uint32_t SB = 8192u;
    int tid = threadIdx.x, wid = tid >> 5, lane = tid & 31;
    int wm = wid >> 2, wn = wid & 3;          // 2(M) x 4(N)
    int m0 = blockIdx.x * 64;
    int bh = m0 >> 11;

    {
        const f16* Ab = A + (size_t)m0 * 64;
#pragma unroll
        for (int i = 0; i < 2; i++) {
            int idx = i*256 + tid; int r = idx >> 3, g = idx & 7;
            cp16(sb + r*128 + ((g ^ (r & 7)) << 4), Ab + r*64 + g*8);
        }
        const f16* Bb = Bhi + (size_t)bh * ws;
#pragma unroll
        for (int i = 0; i < 8; i++) {
            int idx = i*256 + tid; int r = idx >> 3, g = idx & 7;
            cp16(sb + SB + r*128 + ((g ^ (r & 7)) << 4), Bb + r*64 + g*8);
        }
        if (MODE == 2) {
            const f16* B2 = Blo + (size_t)bh * ws;
#pragma unroll
            for (int i = 0; i < 8; i++) {
                int idx = i*256 + tid; int r = idx >> 3, g = idx & 7;
                cp16(sb + SB + 32768 + r*128 + ((g ^ (r & 7)) << 4), B2 + r*64 + g*8);
            }
        }
    }
    asm volatile("cp.async.commit_group;\ncp.async.wait_group 0;" ::: "memory");
    __syncthreads();

    float acc[2][8][4];
#pragma unroll
    for (int mt = 0; mt < 2; mt++)
#pragma unroll
        for (int nt = 0; nt < 8; nt++)
#pragma unroll
            for (int e = 0; e < 4; e++) acc[mt][nt][e] = 0.f;

#pragma unroll
    for (int kk = 0; kk < 4; kk++) {
        uint32_t a[2][4];
#pragma unroll
        for (int mt = 0; mt < 2; mt++) {
            int r = wm*32 + mt*16 + (lane & 7) + ((lane >> 3) & 1) * 8;
            int cch = kk*2 + (lane >> 4);
            ldsm4(a[mt], sb + r*128 + ((cch ^ (r & 7)) << 4));
        }
        uint32_t bh_r[8][2], bl_r[8][2];
#pragma unroll
        for (int np = 0; np < 4; np++) {
            int r = wn*64 + np*16 + (lane & 7) + ((lane >> 4) & 1) * 8;
            int cch = kk*2 + ((lane >> 3) & 1);
            uint32_t off = r*128 + ((cch ^ (r & 7)) << 4);
            uint32_t d[4];
            ldsm4(d, sb + SB + off);
            bh_r[2*np][0]=d[0]; bh_r[2*np][1]=d[1];
            bh_r[2*np+1][0]=d[2]; bh_r[2*np+1][1]=d[3];
            if (MODE == 2) {
                ldsm4(d, sb + SB + 32768 + off);
                bl_r[2*np][0]=d[0]; bl_r[2*np][1]=d[1];
                bl_r[2*np+1][0]=d[2]; bl_r[2*np+1][1]=d[3];
            }
        }
#pragma unroll
        for (int mt = 0; mt < 2; mt++)
#pragma unroll
            for (int nt = 0; nt < 8; nt++) {
                mma_h(acc[mt][nt], a[mt], bh_r[nt]);
                if (MODE == 2) mma_h(acc[mt][nt], a[mt], bl_r[nt]);
            }
    }

#pragma unroll
    for (int mt = 0; mt < 2; mt++) {
        int mrow = m0 + wm*32 + mt*16 + (lane >> 2);
#pragma unroll
        for (int nt = 0; nt < 8; nt++) {
            int c = wn*64 + nt*8 + (lane & 3) * 2;
#pragma unroll
            for (int half = 0; half < 2; half++) {
                size_t off = (size_t)(mrow + half*8) * 256 + c;
                float v0 = acc[mt][nt][half*2], v1 = acc[mt][nt][half*2 + 1];
                if (MODE == 0) {
                    *(__half2*)&o1[off] = __floats2half2_rn(v0, v1);
                    *(__half2*)&o2[off] = __floats2half2_rn(geluf(v0), geluf(v1));
                } else if (MODE == 1) {
                    __half2 p2 = *(const __half2*)&o2[off];
                    float2 pf = __half22float2(p2);
                    *(__half2*)&o1[off] =
                        __floats2half2_rn(v0 * gelugrad(pf.x), v1 * gelugrad(pf.y));
                } else {
                    *(__half2*)&o1[off] = __floats2half2_rn(geluf(v0), geluf(v1));
                }
            }
        }
    }
}

// ======== MLP GEMM 2 (store) + fused pf_rmsnorm bwd -> dhb =================
// C = h1 @ mW1; then per 64-col row: rms, hn, dp = 2theta(hn + k - v),
// dy = sum dp*hn, dh = (dp - hn*dy/64)/rms.  smem: A 2x16K, B 32K, red 2x1K.
#define M1S_SMEM (32768 + 32768 + 2048)
__global__ void __launch_bounds__(256)
k_mlp1s(const f16* __restrict__ A, const f16* __restrict__ Bw,
        const f16* __restrict__ keysb, const f16* __restrict__ valh,
        f16* __restrict__ dhb) {
    extern __shared__ char sm[];
    uint32_t sb = smem_u32(sm);
    constexpr uint32_t SB = 32768u;
    float* RED1 = (float*)(sm + 65536);        // [128][2]
    float* RED2 = RED1 + 256;                  // [128][2]
    int tid = threadIdx.x, wid = tid >> 5, lane = tid & 31;
    int wm = wid >> 1, wn = wid & 1;
    int m0 = blockIdx.x * 128;

    {
        const f16* Bb = Bw;
#pragma unroll
        for (int i = 0; i < 8; i++) {
            int idx = i*256 + tid; int r = idx >> 5, g = idx & 31;
            cp16(sb + SB + r*512 + ((g ^ (r & 7)) << 4), Bb + r*256 + g*8);
        }
    }
#define LA1(CH, ST) do {                                                       \
    uint32_t _a = sb + (ST) * 16384u;                                          \
    _Pragma("unroll")                                                          \
    for (int i = 0; i < 4; i++) {                                              \
        int idx = i*256 + tid; int r = idx >> 3, g = idx & 7;                  \
        cp16(_a + r*128 + ((g ^ (r & 7)) << 4),                                \
             A + (size_t)(m0 + r)*256 + (CH)*64 + g*8);                        \
    }                                                                          \
    asm volatile("cp.async.commit_group;" ::: "memory");                       \
} while (0)

    LA1(0, 0);
    float acc[2][4][4];
#pragma unroll
    for (int mt = 0; mt < 2; mt++)
#pragma unroll
        for (int nt = 0; nt < 4; nt++)
#pragma unroll
            for (int e = 0; e < 4; e++) acc[mt][nt][e] = 0.f;

    for (int ch = 0; ch < 4; ch++) {
        if (ch < 3) {
            LA1(ch + 1, (ch + 1) & 1);
            asm volatile("cp.async.wait_group 1;" ::: "memory");
        } else {
            asm volatile("cp.async.wait_group 0;" ::: "memory");
        }
        __syncthreads();
        uint32_t sA = sb + (ch & 1) * 16384u;
#pragma unroll
        for (int kk = 0; kk < 4; kk++) {
            uint32_t a[2][4];
#pragma unroll
            for (int mt = 0; mt < 2; mt++) {
                int r = wm*32 + mt*16 + (lane & 7) + ((lane >> 3) & 1) * 8;
                int cch = kk*2 + (lane >> 4);
                ldsm4(a[mt], sA + r*128 + ((cch ^ (r & 7)) << 4));
            }
            uint32_t b_r[4][2];
#pragma unroll
            for (int np = 0; np < 2; np++) {
                int r = wn*32 + np*16 + (lane & 7) + ((lane >> 4) & 1) * 8;
                int kg = ch*8 + kk*2 + ((lane >> 3) & 1);
                uint32_t d[4];
                ldsm4(d, sb + SB + r*512 + ((kg ^ (r & 7)) << 4));
                b_r[2*np][0]=d[0]; b_r[2*np][1]=d[1];
                b_r[2*np+1][0]=d[2]; b_r[2*np+1][1]=d[3];
            }
#pragma unroll
            for (int mt = 0; mt < 2; mt++)
#pragma unroll
                for (int nt = 0; nt < 4; nt++)
                    mma_h(acc[mt][nt], a[mt], b_r[nt]);
        }
        __syncthreads();
    }

    // ---- fused pf_rmsnorm fwd+bwd epilogue ----
    // phase 1: row sum of squares
#pragma unroll
    for (int mt = 0; mt < 2; mt++)
#pragma unroll
        for (int half = 0; half < 2; half++) {
            float s = 0.f;
#pragma unroll
            for (int nt = 0; nt < 4; nt++) {
                float v0 = acc[mt][nt][half*2], v1 = acc[mt][nt][half*2+1];
                s += v0*v0 + v1*v1;
            }
            s += __shfl_xor_sync(0xffffffffu, s, 1);
            s += __shfl_xor_sync(0xffffffffu, s, 2);
            int rl = wm*32 + mt*16 + half*8 + (lane >> 2);
            if ((lane & 3) == 0) RED1[rl*2 + wn] = s;
        }
    __syncthreads();

    // phase 2: dp partial dy
    float rmsv[2][2], th[2][2];
    uint32_t k2[2][2][4], v2[2][2][4];
#pragma unroll
    for (int mt = 0; mt < 2; mt++)
#pragma unroll
        for (int half = 0; half < 2; half++) {
            int rl = wm*32 + mt*16 + half*8 + (lane >> 2);
            int mrow = m0 + rl;
            float tot = RED1[rl*2] + RED1[rl*2+1];
            float rms = sqrtf(tot / 64.f + 1e-8f);
            rmsv[mt][half] = rms;
            th[mt][half] = g_theta[mrow];
            float dy = 0.f;
#pragma unroll
            for (int nt = 0; nt < 4; nt++) {
                int c = wn*32 + nt*8 + (lane & 3)*2;
                size_t off = (size_t)mrow*64 + c;
                __half2 kk2 = *(const __half2*)&keysb[off];
                __half2 vv2 = *(const __half2*)&valh[off];
                k2[mt][half][nt] = *(uint32_t*)&kk2;
                v2[mt][half][nt] = *(uint32_t*)&vv2;
                float2 kf = __half22float2(kk2), vf = __half22float2(vv2);
                float hn0 = acc[mt][nt][half*2]   / rms;
                float hn1 = acc[mt][nt][half*2+1] / rms;
                float dp0 = 2.f * th[mt][half] * (hn0 + kf.x - vf.x);
                float dp1 = 2.f * th[mt][half] * (hn1 + kf.y - vf.y);
                dy += dp0*hn0 + dp1*hn1;
            }
            dy += __shfl_xor_sync(0xffffffffu, dy, 1);
            dy += __shfl_xor_sync(0xffffffffu, dy, 2);
            if ((lane & 3) == 0) RED2[rl*2 + wn] = dy;
        }
    __syncthreads();

    // phase 3: dh
#pragma unroll
    for (int mt = 0; mt < 2; mt++)
#pragma unroll
        for (int half = 0; half < 2; half++) {
            int rl = wm*32 + mt*16 + half*8 + (lane >> 2);
            int mrow = m0 + rl;
            float rms = rmsv[mt][half];
            float t = th[mt][half];
            float dy = (RED2[rl*2] + RED2[rl*2+1]) / 64.f;
#pragma unroll
            for (int nt = 0; nt < 4; nt++) {
                int c = wn*32 + nt*8 + (lane & 3)*2;
                uint32_t ku = k2[mt][half][nt], vu = v2[mt][half][nt];
                float2 kf = __half22float2(*(__half2*)&ku);
                float2 vf = __half22float2(*(__half2*)&vu);
                float hn0 = acc[mt][nt][half*2]   / rms;
                float hn1 = acc[mt][nt][half*2+1] / rms;
                float dp0 = 2.f * t * (hn0 + kf.x - vf.x);
                float dp1 = 2.f * t * (hn1 + kf.y - vf.y);
                float dh0 = (dp0 - hn0 * dy) / rms;
                float dh1 = (dp1 - hn1 * dy) / rms;
                *(__half2*)&dhb[(size_t)mrow*64 + c] = __floats2half2_rn(dh0, dh1);
            }
        }
#undef LA1
}

// ======== MLP GEMM 2 (retrieve) + fused nan_to_num/pf_rmsnorm/residual =====
// out = hn + q, split-head store.  smem: A 2x16K, B 64K, red 1K.
#define M1R_SMEM (32768 + 65536 + 1024)
__global__ void __launch_bounds__(256)
k_mlp1r(const f16* __restrict__ A, const f16* __restrict__ Bhi,
        const f16* __restrict__ Blo, long long ws,
        const float* __restrict__ qres, float* __restrict__ out) {
    extern __shared__ char sm[];
    uint32_t sb = smem_u32(sm);
    constexpr uint32_t SB = 32768u;
    float* RED1 = (float*)(sm + 98304);        // [128][2]
    int tid = threadIdx.x, wid = tid >> 5, lane = tid & 31;
    int wm = wid >> 1, wn = wid & 1;
    int m0 = blockIdx.x * 128;
    int bh = m0 >> 11;

    {
        const f16* Bb = Bhi + (size_t)bh * ws;
#pragma unroll
        for (int i = 0; i < 8; i++) {
            int idx = i*256 + tid; int r = idx >> 5, g = idx & 31;
            cp16(sb + SB + r*512 + ((g ^ (r & 7)) << 4), Bb + r*256 + g*8);
        }
        const f16* B2 = Blo + (size_t)bh * ws;
#pragma unroll
        for (int i = 0; i < 8; i++) {
            int idx = i*256 + tid; int r = idx >> 5, g = idx & 31;
            cp16(sb + SB + 32768 + r*512 + ((g ^ (r & 7)) << 4), B2 + r*256 + g*8);
        }
    }
#define LA2(CH, ST) do {                                                       \
    uint32_t _a = sb + (ST) * 16384u;                                          \
    _Pragma("unroll")                                                          \
    for (int i = 0; i < 4; i++) {                                              \
        int idx = i*256 + tid; int r = idx >> 3, g = idx & 7;                  \
        cp16(_a + r*128 + ((g ^ (r & 7)) << 4),                                \
             A + (size_t)(m0 + r)*256 + (CH)*64 + g*8);                        \
    }                                                                          \
    asm volatile("cp.async.commit_group;" ::: "memory");                       \
} while (0)

    LA2(0, 0);
    float acc[2][4][4];
#pragma unroll
    for (int mt = 0; mt < 2; mt++)
#pragma unroll
        for (int nt = 0; nt < 4; nt++)
#pragma unroll
            for (int e = 0; e < 4; e++) acc[mt][nt][e] = 0.f;

    for (int ch = 0; ch < 4; ch++) {
        if (ch < 3) {
            LA2(ch + 1, (ch + 1) & 1);
            asm volatile("cp.async.wait_group 1;" ::: "memory");
        } else {
            asm volatile("cp.async.wait_group 0;" ::: "memory");
        }
        __syncthreads();
        uint32_t sA = sb + (ch & 1) * 16384u;
#pragma unroll
        for (int kk = 0; kk < 4; kk++) {
            uint32_t a[2][4];
#pragma unroll
            for (int mt = 0; mt < 2; mt++) {
                int r = wm*32 + mt*16 + (lane & 7) + ((lane >> 3) & 1) * 8;
                int cch = kk*2 + (lane >> 4);
                ldsm4(a[mt], sA + r*128 + ((cch ^ (r & 7)) << 4));
            }
            uint32_t bh_r[4][2], bl_r[4][2];
#pragma unroll
            for (int np = 0; np < 2; np++) {
                int r = wn*32 + np*16 + (lane & 7) + ((lane >> 4) & 1) * 8;
                int kg = ch*8 + kk*2 + ((lane >> 3) & 1);
                uint32_t off = r*512 + ((kg ^ (r & 7)) << 4);
                uint32_t d[4];
                ldsm4(d, sb + SB + off);
                bh_r[2*np][0]=d[0]; bh_r[2*np][1]=d[1];
                bh_r[2*np+1][0]=d[2]; bh_r[2*np+1][1]=d[3];
                ldsm4(d, sb + SB + 32768 + off);
                bl_r[2*np][0]=d[0]; bl_r[2*np][1]=d[1];
                bl_r[2*np+1][0]=d[2]; bl_r[2*np+1][1]=d[3];
            }
#pragma unroll
            for (int mt = 0; mt < 2; mt++)
#pragma unroll
                for (int nt = 0; nt < 4; nt++) {
                    mma_h(acc[mt][nt], a[mt], bh_r[nt]);
                    mma_h(acc[mt][nt], a[mt], bl_r[nt]);
                }
        }
        __syncthreads();
    }

    // ---- fused nan_to_num + pf_rmsnorm + residual + split-head store ----
#pragma unroll
    for (int mt = 0; mt < 2; mt++)
#pragma unroll
        for (int nt = 0; nt < 4; nt++)
#pragma unroll
            for (int e = 0; e < 4; e++)
                if (!isfinite(acc[mt][nt][e])) acc[mt][nt][e] = 0.f;

#pragma unroll
    for (int mt = 0; mt < 2; mt++)
#pragma unroll
        for (int half = 0; half < 2; half++) {
            float s = 0.f;
#pragma unroll
            for (int nt = 0; nt < 4; nt++) {
                float v0 = acc[mt][nt][half*2], v1 = acc[mt][nt][half*2+1];
                s += v0*v0 + v1*v1;
            }
            s += __shfl_xor_sync(0xffffffffu, s, 1);
            s += __shfl_xor_sync(0xffffffffu, s, 2);
            int rl = wm*32 + mt*16 + half*8 + (lane >> 2);
            if ((lane & 3) == 0) RED1[rl*2 + wn] = s;
        }
    __syncthreads();

    int bb = bh >> 4, hh = bh & 15;
#pragma unroll
    for (int mt = 0; mt < 2; mt++)
#pragma unroll
        for (int half = 0; half < 2; half++) {
            int rl = wm*32 + mt*16 + half*8 + (lane >> 2);
            int mrow = m0 + rl;
            int s = mrow & 2047;
            float rms = sqrtf((RED1[rl*2] + RED1[rl*2+1]) / 64.f + 1e-8f);
            size_t ob = ((size_t)(bb*Sv + s))*Dv + hh*64;
#pragma unroll
            for (int nt = 0; nt < 4; nt++) {
                int c = wn*32 + nt*8 + (lane & 3)*2;
                float2 qv = *(const float2*)&qres[(size_t)mrow*64 + c];
                float o0 = acc[mt][nt][half*2]   / rms + qv.x;
                float o1 = acc[mt][nt][half*2+1] / rms + qv.y;
                *(float2*)&out[ob + c] = make_float2(o0, o1);
            }
        }
#undef LA2
}

// ======== gradT ============================================================
template <int MI, int NO>
__global__ void __launch_bounds__(256)
k_gradmma(const f16* __restrict__ A, const f16* __restrict__ Bm,
          float* __restrict__ G) {
    __shared__ __align__(16) char sm[32768];
    uint32_t sb = smem_u32(sm);
    int tid = threadIdx.x, wid = tid >> 5, lane = tid & 31;
    int wm = wid >> 2, wn = wid & 3;
    int bh = blockIdx.z;
    int m0 = blockIdx.y * 64, n0 = blockIdx.x * 64;
    const f16* Ab = A  + ((size_t)bh * Sv) * MI + m0;
    const f16* Bb = Bm + ((size_t)bh * Sv) * NO + n0;

#define LG(ST, S0) do {                                                        \
    _Pragma("unroll")                                                          \
    for (int i = 0; i < 2; i++) {                                              \
        int idx = i*256 + tid; int r = idx >> 3, g = idx & 7;                  \
        cp16(sb + (ST)*8192 + r*128 + ((g ^ (r & 7)) << 4),                    \
             Ab + (size_t)((S0) + r)*MI + g*8);                                \
        cp16(sb + 16384 + (ST)*8192 + r*128 + ((g ^ (r & 7)) << 4),            \
             Bb + (size_t)((S0) + r)*NO + g*8);                                \
    }                                                                          \
    asm volatile("cp.async.commit_group;" ::: "memory");                       \
} while (0)

    LG(0, 0);
    float acc[2][2][4];
#pragma unroll
    for (int mt = 0; mt < 2; mt++)
#pragma unroll
        for (int nt = 0; nt < 2; nt++)
#pragma unroll
            for (int e = 0; e < 4; e++) acc[mt][nt][e] = 0.f;

    for (int st = 0; st < 32; st++) {
        if (st < 31) {
            LG((st + 1) & 1, (st + 1) * 64);
            asm volatile("cp.async.wait_group 1;" ::: "memory");
        } else {
            asm volatile("cp.async.wait_group 0;" ::: "memory");
        }
        __syncthreads();
        uint32_t sA = sb + (st & 1) * 8192;
        uint32_t sB = sb + 16384 + (st & 1) * 8192;
#pragma unroll
        for (int kk = 0; kk < 4; kk++) {
            uint32_t aT[2][4];
#pragma unroll
            for (int mt = 0; mt < 2; mt++) {
                int row = kk*16 + (lane & 7) + ((lane >> 4) & 1) * 8;
                int cg = wm*4 + mt*2 + ((lane >> 3) & 1);
                ldsm4t(aT[mt], sA + row*128 + ((cg ^ (row & 7)) << 4));
            }
            int row = kk*16 + (lane & 7) + ((lane >> 3) & 1) * 8;
            int cg = wn*2 + (lane >> 4);
            uint32_t d[4];
            ldsm4t(d, sB + row*128 + ((cg ^ (row & 7)) << 4));
            uint32_t bT[2][2] = {{d[0], d[1]}, {d[2], d[3]}};
#pragma unroll
            for (int mt = 0; mt < 2; mt++)
#pragma unroll
                for (int nt = 0; nt < 2; nt++)
                    mma_h(acc[mt][nt], aT[mt], bT[nt]);
        }
        __syncthreads();
    }
#pragma unroll
    for (int mt = 0; mt < 2; mt++) {
        int m = m0 + wm*32 + mt*16 + (lane >> 2);
#pragma unroll
        for (int nt = 0; nt < 2; nt++) {
            int n = n0 + wn*16 + nt*8 + (lane & 3) * 2;
            *(float2*)&G[((size_t)bh*MI + m)*NO + n]     = make_float2(acc[mt][nt][0], acc[mt][nt][1]);
            *(float2*)&G[((size_t)bh*MI + m + 8)*NO + n] = make_float2(acc[mt][nt][2], acc[mt][nt][3]);
        }
    }
#undef LG
}

// ---------------- gates: alpha, theta (reads fp16 xn) -----------------------
__global__ void __launch_bounds__(256)
k_gates(const f16* __restrict__ xn,
        const float* __restrict__ aw, const float* __restrict__ ab,
        const float* __restrict__ tw, const float* __restrict__ tb) {
    __shared__ float Xs[64][128];
    __shared__ float Ws[64][32];
    int m0 = blockIdx.x * 128;
    int tid = threadIdx.x;
    int rg = tid >> 3, cg = tid & 7;
    float acc[4][4] = {};
    for (int k0 = 0; k0 < 1024; k0 += 64) {
#pragma unroll
        for (int i = 0; i < 4; i++) {
            int idx = tid + i*256;
            int r = idx >> 3, c8 = idx & 7;
            size_t ga = (size_t)(m0 + r)*1024 + k0 + c8*8;
            uint4 vh = *(const uint4*)&xn[ga];
            __half2 h2[4];
            *(uint4*)h2 = vh;
#pragma unroll
            for (int j = 0; j < 4; j++) {
                float2 fh = __half22float2(h2[j]);
                Xs[c8*8 + 2*j][r]     = fh.x;
                Xs[c8*8 + 2*j + 1][r] = fh.y;
            }
        }
#pragma unroll
        for (int i = 0; i < 2; i++) {
            int idx = tid + i*256;
            int r = idx >> 3, c4 = idx & 7;
            const float* src = (c4 < 4) ? (aw + (size_t)(k0 + r)*16 + c4*4)
                                        : (tw + (size_t)(k0 + r)*16 + (c4 - 4)*4);
            *(float4*)&Ws[r][c4*4] = *(const float4*)src;
        }
        __syncthreads();
#pragma unroll
        for (int k = 0; k < 64; k++) {
            float ra[4], rb[4];
#pragma unroll
            for (int i = 0; i < 4; i++) ra[i] = Xs[k][rg*4 + i];
#pragma unroll
            for (int j = 0; j < 4; j++) rb[j] = Ws[k][cg*4 + j];
#pragma unroll
            for (int i = 0; i < 4; i++)
#pragma unroll
                for (int j = 0; j < 4; j++) acc[i][j] += ra[i] * rb[j];
        }
        __syncthreads();
    }
#pragma unroll
    for (int i = 0; i < 4; i++) {
        int m = m0 + rg*4 + i;
        int b = m >> 11, s = m & 2047;
#pragma unroll
        for (int j = 0; j < 4; j++) {
            int c = cg*4 + j;
            int h = c & 15;
            size_t off = ((size_t)(b*Hv + h))*Sv + s;
            if (c < 16) g_alpha[off] = 1.f / (1.f + expf(-(acc[i][j] + ab[h])));
            else        g_theta[off] = 0.01f / (1.f + expf(-(acc[i][j] + tb[h])));
        }
    }
}

// ---------------- per-bh reductions -----------------------------------------
__global__ void k_amean() {
    int bh = blockIdx.x; int tid = threadIdx.x;
    float s = 0.f;
    for (int i = tid; i < Sv; i += 256) s += g_alpha[(size_t)bh*Sv + i];
#pragma unroll
    for (int o = 16; o > 0; o >>= 1) s += __shfl_xor_sync(0xffffffffu, s, o);
    __shared__ float red[8];
    if ((tid & 31) == 0) red[tid >> 5] = s;
    __syncthreads();
    if (tid == 0) {
        float t = 0.f;
#pragma unroll
        for (int i = 0; i < 8; i++) t += red[i];
        g_amean[bh] = t / (float)Sv;
    }
}

__global__ void k_clip() {
    int bh = blockIdx.x; int tid = threadIdx.x;
    const float* a = g_g0 + (size_t)bh * 16384;
    const float* b = g_g1 + (size_t)bh * 16384;
    float s = 0.f;
    for (int i = tid; i < 16384; i += 256) {
        float v = a[i]; s += v*v;
        v = b[i]; s += v*v;
    }
#pragma unroll
    for (int o = 16; o > 0; o >>= 1) s += __shfl_xor_sync(0xffffffffu, s, o);
    __shared__ float red[8];
    if ((tid & 31) == 0) red[tid >> 5] = s;
    __syncthreads();
    if (tid == 0) {
        float t = 0.f;
#pragma unroll
        for (int i = 0; i < 8; i++) t += red[i];
        float c = 10.f / (sqrtf(t) + 1e-6f);
        g_coef[bh] = c < 1.f ? c : 1.f;
    }
}

// ---------------- weight prep + update --------------------------------------
__global__ void k_tr(const float* __restrict__ src, float* __restrict__ dstF,
                     f16* __restrict__ dstB, int R, int C) {
    int idx = blockIdx.x * 256 + threadIdx.x;
    if (idx >= R*C) return;
    int c = idx / R, r = idx % R;
    float v = src[r*C + c];
    dstF[idx] = v;
    dstB[idx] = __float2half(v);
}
__global__ void k_cpb(const float* __restrict__ s, f16* __restrict__ d, int n) {
    int idx = blockIdx.x * 256 + threadIdx.x;
    if (idx < n) d[idx] = __float2half(s[idx]);
}
__global__ void k_newwT(const float* __restrict__ WT, const float* __restrict__ gT,
                        f16* __restrict__ ohi, f16* __restrict__ olo) {
    size_t idx = (size_t)blockIdx.x * 256 + threadIdx.x;
    int bh = (int)(idx >> 14); int e = (int)(idx & 16383);
    float w = WT[e];
    float nw = (1.f - g_amean[bh]) * w - g_coef[bh] * gT[idx];
    if (!isfinite(nw)) nw = w;
    f16 h = __float2half(nw);
    ohi[idx] = h;
    olo[idx] = __float2half(nw - __half2float(h));
}

// ============================================================================
extern "C" void kernel_launch(void* const* d_in, const int* in_sizes, int n_in,
                              void* d_out, int out_size) {
    (void)in_sizes; (void)n_in; (void)out_size;
    const float* x   = (const float*)d_in[0];
    const float* W_K = (const float*)d_in[1];
    const float* W_V = (const float*)d_in[2];
    const float* W_Q = (const float*)d_in[3];
    const float* mW0 = (const float*)d_in[4];
    const float* mW1 = (const float*)d_in[5];
    const float* knw = (const float*)d_in[6];
    const float* qnw = (const float*)d_in[7];
    const float* snw = (const float*)d_in[8];
    const float* rnw = (const float*)d_in[9];
    const float* aw  = (const float*)d_in[10];
    const float* ab  = (const float*)d_in[11];
    const float* tw  = (const float*)d_in[12];
    const float* tb  = (const float*)d_in[13];
    float* out = (float*)d_out;

    f16 *xnh, *wkv, *wqhi, *wqlo, *keysb, *qh, *dhb, *valh;
    f16 *mW0Tb, *mW1Tb, *mW1b, *nW0Thi, *nW0Tlo, *nW1Thi, *nW1Tlo;
    float *q, *g0p, *g1p, *mW0T, *mW1T;
    char* pool;
    cudaGetSymbolAddress((void**)&xnh,    g_xnh);
    cudaGetSymbolAddress((void**)&wkv,    g_wkv);
    cudaGetSymbolAddress((void**)&wqhi,   g_wqhi);
    cudaGetSymbolAddress((void**)&wqlo,   g_wqlo);
    cudaGetSymbolAddress((void**)&valh,   g_values);
    cudaGetSymbolAddress((void**)&q,      g_q);
    cudaGetSymbolAddress((void**)&keysb,  g_keysb);
    cudaGetSymbolAddress((void**)&qh,     g_qh);
    cudaGetSymbolAddress((void**)&dhb,    g_dhb);
    cudaGetSymbolAddress((void**)&pool,   g_pool);
    cudaGetSymbolAddress((void**)&g0p,    g_g0);
    cudaGetSymbolAddress((void**)&g1p,    g_g1);
    cudaGetSymbolAddress((void**)&mW0T,   g_mW0T);
    cudaGetSymbolAddress((void**)&mW1T,   g_mW1T);
    cudaGetSymbolAddress((void**)&mW0Tb,  g_mW0Tb);
    cudaGetSymbolAddress((void**)&mW1Tb,  g_mW1Tb);
    cudaGetSymbolAddress((void**)&mW1b,   g_mW1b);
    cudaGetSymbolAddress((void**)&nW0Thi, g_nW0Thi);
    cudaGetSymbolAddress((void**)&nW0Tlo, g_nW0Tlo);
    cudaGetSymbolAddress((void**)&nW1Thi, g_nW1Thi);
    cudaGetSymbolAddress((void**)&nW1Tlo, g_nW1Tlo);

    f16* pre0h = (f16*)(pool);
    f16* h1h   = (f16*)(pool + 134217728);
    f16* dh0h  = (f16*)(pool + 268435456);
    f16* h1rh  = (f16*)(pool);                // aliases pre0h (dead by then)

    cudaFuncSetAttribute(k_gemm_kv, cudaFuncAttributeMaxDynamicSharedMemorySize, KV_SMEM);
    cudaFuncSetAttribute(k_gemm_q,  cudaFuncAttributeMaxDynamicSharedMemorySize, Q_SMEM);
    cudaFuncSetAttribute(k_mlp0<0>, cudaFuncAttributeMaxDynamicSharedMemorySize, 40960);
    cudaFuncSetAttribute(k_mlp0<1>, cudaFuncAttributeMaxDynamicSharedMemorySize, 40960);
    cudaFuncSetAttribute(k_mlp0<2>, cudaFuncAttributeMaxDynamicSharedMemorySize, 73728);
    cudaFuncSetAttribute(k_mlp1s,   cudaFuncAttributeMaxDynamicSharedMemorySize, M1S_SMEM);
    cudaFuncSetAttribute(k_mlp1r,   cudaFuncAttributeMaxDynamicSharedMemorySize, M1R_SMEM);

    dim3 gws(32, 32), bws(32, 8);

    // ---- weight prep (independent) ----
    k_tr<<<64, 256>>>(mW0, mW0T, mW0Tb, HDv, HIDv);   // -> [256][64]
    k_tr<<<64, 256>>>(mW1, mW1T, mW1Tb, HIDv, HDv);   // -> [64][256]
    k_cpb<<<64, 256>>>(mW1, mW1b, HIDv*HDv);

    // ---- store path ----
    k_rmsnorm16<<<Mv, 256>>>(x, snw, xnh);
    k_wt16<<<gws, bws>>>(W_K, wkv);
    k_wt16<<<gws, bws>>>(W_V, wkv + (size_t)Dv*Dv);
    k_gemm_kv<<<dim3(16, 128), 256, KV_SMEM>>>(xnh, wkv, keysb, valh, knw);
    k_gates<<<Mv/128, 256>>>(xnh, aw, ab, tw, tb);
    k_amean<<<BHv, 256>>>();

    k_mlp0<0><<<MTv/64, 256, 40960>>>(keysb, mW0Tb, nullptr, 0, pre0h, h1h);
    k_mlp1s<<<MTv/128, 256, M1S_SMEM>>>(h1h, mW1Tb, keysb, valh, dhb);
    // dh0 written in place over pre0h (same-thread same-offset read/write)
    k_mlp0<1><<<MTv/64, 256, 40960>>>(dhb, mW1b, nullptr, 0, dh0h, pre0h);

    k_gradmma<HDv, HIDv><<<dim3(4, 1, BHv), 256>>>(dhb, h1h, g1p);     // g1^T [64][256]
    k_gradmma<HIDv, HDv><<<dim3(1, 4, BHv), 256>>>(dh0h, keysb, g0p);  // g0^T [256][64]
    k_clip<<<BHv, 256>>>();
    k_newwT<<<(BHv*16384)/256, 256>>>(mW0T, g0p, nW0Thi, nW0Tlo);
    k_newwT<<<(BHv*16384)/256, 256>>>(mW1T, g1p, nW1Thi, nW1Tlo);

    // ---- retrieve path ----
    k_rmsnorm16<<<Mv, 256>>>(x, rnw, xnh);
    k_wt2<<<gws, bws>>>(W_Q, wqhi, wqlo);
    k_gemm_q<<<dim3(8, 128), 256, Q_SMEM>>>(xnh, wqhi, wqlo, q, qh, qnw);
    k_mlp0<2><<<MTv/64, 256, 73728>>>(qh, nW0Thi, nW0Tlo,
                                      (long long)HIDv*HDv, h1rh, nullptr);
    k_mlp1r<<<MTv/128, 256, M1R_SMEM>>>(h1rh, nW1Thi, nW1Tlo,
                                        (long long)HDv*HIDv, q, out);
}

// round 15
// speedup vs baseline: 2.3779x; 1.1277x over previous
#include <cuda_runtime.h>
#include <cuda_bf16.h>
#include <cuda_fp16.h>
#include <math.h>
#include <stdint.h>

// Problem constants
#define Bv   8
#define Sv   2048
#define Dv   1024
#define Hv   16
#define HDv  64
#define HIDv 256
#define BHv  128               // B*H
#define Mv   (Bv*Sv)           // 16384 rows of x
#define MTv  (BHv*Sv)          // 262144 rows per-head

typedef __half f16;

// ------------------------- scratch (device globals) -------------------------
__device__ f16  g_xnh[Mv*Dv];         // 32 MB
__device__ f16  g_wkv[2*Dv*Dv];       // 4 MB (W_K^T | W_V^T)
__device__ f16  g_wq[Dv*Dv];          // 2 MB (W_Q^T)
__device__ f16  g_values[MTv*HDv];    // 32 MB
__device__ float g_q[MTv*HDv];        // 64 MB (normed q, fp32 residual)
__device__ f16  g_keysb[MTv*HDv];     // 32 MB
__device__ f16  g_qh[MTv*HDv];        // 32 MB
__device__ f16  g_dhb[MTv*HDv];       // 32 MB
// pooled scratch: pre0h@0, h1h@128M, dh0h@256M; retrieve: h1rh@0
__device__ __align__(256) char g_pool[402653184];   // 384 MB
__device__ float g_alpha[BHv*Sv];
__device__ float g_theta[BHv*Sv];
__device__ float g_amean[BHv];
__device__ float g_coef[BHv];
__device__ float g_g0[BHv*HIDv*HDv];
__device__ float g_g1[BHv*HDv*HIDv];
__device__ float g_mW0T[HIDv*HDv];    __device__ f16 g_mW0Tb[HIDv*HDv];
__device__ float g_mW1T[HDv*HIDv];    __device__ f16 g_mW1Tb[HDv*HIDv];
__device__ f16 g_mW1b[HIDv*HDv];
__device__ f16 g_nW0T[BHv*HIDv*HDv];
__device__ f16 g_nW1T[BHv*HDv*HIDv];

// ========================= mma.sync helpers =================================
__device__ __forceinline__ uint32_t smem_u32(const void* p) {
    uint32_t a;
    asm("{ .reg .u64 t; cvta.to.shared.u64 t, %1; cvt.u32.u64 %0, t; }"
        : "=r"(a) : "l"(p));
    return a;
}
__device__ __forceinline__ void ldsm4(uint32_t* d, uint32_t addr) {
    asm volatile("ldmatrix.sync.aligned.m8n8.x4.shared.b16 {%0,%1,%2,%3}, [%4];"
                 : "=r"(d[0]), "=r"(d[1]), "=r"(d[2]), "=r"(d[3]) : "r"(addr));
}
__device__ __forceinline__ void ldsm4t(uint32_t* d, uint32_t addr) {
    asm volatile("ldmatrix.sync.aligned.m8n8.x4.trans.shared.b16 {%0,%1,%2,%3}, [%4];"
                 : "=r"(d[0]), "=r"(d[1]), "=r"(d[2]), "=r"(d[3]) : "r"(addr));
}
__device__ __forceinline__ void mma_h(float* c, const uint32_t* a, const uint32_t* b) {
    asm volatile("mma.sync.aligned.m16n8k16.row.col.f32.f16.f16.f32 "
                 "{%0,%1,%2,%3}, {%4,%5,%6,%7}, {%8,%9}, {%0,%1,%2,%3};"
                 : "+f"(c[0]), "+f"(c[1]), "+f"(c[2]), "+f"(c[3])
                 : "r"(a[0]), "r"(a[1]), "r"(a[2]), "r"(a[3]), "r"(b[0]), "r"(b[1]));
}
__device__ __forceinline__ void cp16(uint32_t dst, const void* src) {
    asm volatile("cp.async.cg.shared.global [%0], [%1], 16;" :: "r"(dst), "l"(src) : "memory");
}
__device__ __forceinline__ float geluf(float v) {
    return 0.5f * v * (1.f + erff(v * 0.70710678118654752f));
}
__device__ __forceinline__ float gelugrad(float p) {
    float cdf = 0.5f * (1.f + erff(p * 0.70710678118654752f));
    float pdf = expf(-0.5f * p * p) * 0.3989422804014327f;
    return cdf + p * pdf;
}

// ---------------- rmsnorm over D=1024 rows, emit fp16 -----------------------
__global__ void k_rmsnorm16(const float* __restrict__ x, const float* __restrict__ w,
                            f16* __restrict__ o) {
    int row = blockIdx.x;
    const float* xr = x + (size_t)row * Dv;
    int tid = threadIdx.x;
    float v[4]; float ss = 0.f;
#pragma unroll
    for (int i = 0; i < 4; i++) { v[i] = xr[tid + i*256]; ss += v[i]*v[i]; }
#pragma unroll
    for (int o2 = 16; o2 > 0; o2 >>= 1) ss += __shfl_xor_sync(0xffffffffu, ss, o2);
    __shared__ float red[8];
    __shared__ float rinv;
    if ((tid & 31) == 0) red[tid >> 5] = ss;
    __syncthreads();
    if (tid == 0) {
        float t = 0.f;
#pragma unroll
        for (int i = 0; i < 8; i++) t += red[i];
        rinv = rsqrtf(t / (float)Dv + 1e-6f);
    }
    __syncthreads();
    float r = rinv;
#pragma unroll
    for (int i = 0; i < 4; i++)
        o[(size_t)row*Dv + tid + i*256] = __float2half(v[i] * w[tid + i*256] * r);
}

// ---------------- transpose weight -> fp16 (single) -------------------------
__global__ void k_wt16(const float* __restrict__ W, f16* __restrict__ T) {
    __shared__ float t[32][33];
    int k0 = blockIdx.y * 32, n0 = blockIdx.x * 32;
    int tx = threadIdx.x, ty = threadIdx.y;
#pragma unroll
    for (int r = 0; r < 4; r++)
        t[ty + r*8][tx] = W[(size_t)(k0 + ty + r*8)*Dv + n0 + tx];
    __syncthreads();
#pragma unroll
    for (int r = 0; r < 4; r++)
        T[(size_t)(n0 + ty + r*8)*Dv + k0 + tx] = __float2half(t[tx][ty + r*8]);
}

// ===== fused K+V GEMM: (16384x1024)@(1024x2048) fp16 single-pass ============
#define KV_SMEM (2*32768)
__global__ void __launch_bounds__(256)
k_gemm_kv(const f16* __restrict__ A, const f16* __restrict__ Bw,
          f16* __restrict__ keysb, f16* __restrict__ valh,
          const float* __restrict__ knw) {
    extern __shared__ char smem[];
    uint32_t sb = smem_u32(smem);
    int tid = threadIdx.x;
    int wid = tid >> 5, lane = tid & 31;
    int wm = wid >> 1, wn = wid & 1;
    int m0 = blockIdx.y * 128, n0 = blockIdx.x * 128;

#define LOAD_KV(CH, ST) do {                                                   \
    int _k0 = (CH) * 64;                                                       \
    uint32_t _sb = sb + (ST) * 32768;                                          \
    _Pragma("unroll")                                                          \
    for (int i = 0; i < 8; i++) {                                              \
        int idx = i * 256 + tid;                                               \
        int layer = idx >> 10, rem = idx & 1023;                               \
        int r = rem >> 3, g = rem & 7;                                         \
        const f16* src = layer ? Bw + (size_t)(n0 + r) * Dv + _k0 + g * 8      \
                               : A  + (size_t)(m0 + r) * Dv + _k0 + g * 8;     \
        cp16(_sb + layer * 16384 + r * 128 + ((g ^ (r & 7)) << 4), src);       \
    }                                                                          \
    asm volatile("cp.async.commit_group;" ::: "memory");                       \
} while (0)

    LOAD_KV(0, 0);
    float acc[2][8][4];
#pragma unroll
    for (int mt = 0; mt < 2; mt++)
#pragma unroll
        for (int nt = 0; nt < 8; nt++)
#pragma unroll
            for (int e = 0; e < 4; e++) acc[mt][nt][e] = 0.f;

    for (int ch = 0; ch < 16; ch++) {
        if (ch < 15) {
            LOAD_KV(ch + 1, (ch + 1) & 1);
            asm volatile("cp.async.wait_group 1;" ::: "memory");
        } else {
            asm volatile("cp.async.wait_group 0;" ::: "memory");
        }
        __syncthreads();
        uint32_t sA = sb + (ch & 1) * 32768;
        uint32_t sB = sA + 16384;
#pragma unroll
        for (int kk = 0; kk < 4; kk++) {
            uint32_t a[2][4];
#pragma unroll
            for (int mt = 0; mt < 2; mt++) {
                int r = wm*32 + mt*16 + (lane & 7) + ((lane >> 3) & 1) * 8;
                int cch = kk*2 + (lane >> 4);
                ldsm4(a[mt], sA + r*128 + ((cch ^ (r & 7)) << 4));
            }
            uint32_t b[8][2];
#pragma unroll
            for (int np = 0; np < 4; np++) {
                int r = wn*64 + np*16 + (lane & 7) + ((lane >> 4) & 1) * 8;
                int cch = kk*2 + ((lane >> 3) & 1);
                uint32_t d[4];
                ldsm4(d, sB + r*128 + ((cch ^ (r & 7)) << 4));
                b[2*np][0]=d[0]; b[2*np][1]=d[1];
                b[2*np+1][0]=d[2]; b[2*np+1][1]=d[3];
            }
#pragma unroll
            for (int mt = 0; mt < 2; mt++)
#pragma unroll
                for (int nt = 0; nt < 8; nt++)
                    mma_h(acc[mt][nt], a[mt], b[nt]);
        }
        __syncthreads();
    }

    int b_ = m0 >> 11;
    int ncol0 = n0 + wn*64;
    bool isK = ncol0 < 1024;
    int h = (isK ? ncol0 : ncol0 - 1024) >> 6;
    float wv[8][2];
    if (isK) {
#pragma unroll
        for (int nt = 0; nt < 8; nt++) {
            int hd = nt*8 + (lane & 3)*2;
            wv[nt][0] = knw[hd]; wv[nt][1] = knw[hd + 1];
        }
    }
#pragma unroll
    for (int mt = 0; mt < 2; mt++) {
#pragma unroll
        for (int half = 0; half < 2; half++) {
            int mrow = m0 + wm*32 + mt*16 + (lane >> 2) + half*8;
            int s = mrow & 2047;
            size_t rb = (((size_t)(b_*Hv + h))*Sv + s)*64;
            if (isK) {
                float ss = 0.f;
#pragma unroll
                for (int nt = 0; nt < 8; nt++) {
                    float v0 = acc[mt][nt][half*2], v1 = acc[mt][nt][half*2+1];
                    ss += v0*v0 + v1*v1;
                }
                ss += __shfl_xor_sync(0xffffffffu, ss, 1);
                ss += __shfl_xor_sync(0xffffffffu, ss, 2);
                float rinv = rsqrtf(ss / 64.f + 1e-6f);
#pragma unroll
                for (int nt = 0; nt < 8; nt++) {
                    int hd = nt*8 + (lane & 3)*2;
                    float v0 = acc[mt][nt][half*2]   * wv[nt][0] * rinv;
                    float v1 = acc[mt][nt][half*2+1] * wv[nt][1] * rinv;
                    *(__half2*)&keysb[rb + hd] = __floats2half2_rn(v0, v1);
                }
            } else {
#pragma unroll
                for (int nt = 0; nt < 8; nt++) {
                    int hd = nt*8 + (lane & 3)*2;
                    *(__half2*)&valh[rb + hd] =
                        __floats2half2_rn(acc[mt][nt][half*2], acc[mt][nt][half*2+1]);
                }
            }
        }
    }
#undef LOAD_KV
}

// ===== Q GEMM: (16384x1024)@(1024x1024), single fp16 ========================
// fused head-rmsnorm(qnw) -> q fp32 + qh fp16
__global__ void __launch_bounds__(256)
k_gemm_q(const f16* __restrict__ A, const f16* __restrict__ Bw,
         float* __restrict__ qout, f16* __restrict__ qh,
         const float* __restrict__ qnw) {
    extern __shared__ char smem[];
    uint32_t sb = smem_u32(smem);
    int tid = threadIdx.x;
    int wid = tid >> 5, lane = tid & 31;
    int wm = wid >> 1, wn = wid & 1;
    int m0 = blockIdx.y * 128, n0 = blockIdx.x * 128;

#define LOAD_Q(CH, ST) do {                                                    \
    int _k0 = (CH) * 64;                                                       \
    uint32_t _sb = sb + (ST) * 32768;                                          \
    _Pragma("unroll")                                                          \
    for (int i = 0; i < 8; i++) {                                              \
        int idx = i * 256 + tid;                                               \
        int layer = idx >> 10, rem = idx & 1023;                               \
        int r = rem >> 3, g = rem & 7;                                         \
        const f16* src = layer ? Bw + (size_t)(n0 + r) * Dv + _k0 + g * 8      \
                               : A  + (size_t)(m0 + r) * Dv + _k0 + g * 8;     \
        cp16(_sb + layer * 16384 + r * 128 + ((g ^ (r & 7)) << 4), src);       \
    }                                                                          \
    asm volatile("cp.async.commit_group;" ::: "memory");                       \
} while (0)

    LOAD_Q(0, 0);
    float acc[2][8][4];
#pragma unroll
    for (int mt = 0; mt < 2; mt++)
#pragma unroll
        for (int nt = 0; nt < 8; nt++)
#pragma unroll
            for (int e = 0; e < 4; e++) acc[mt][nt][e] = 0.f;

    for (int ch = 0; ch < 16; ch++) {
        if (ch < 15) {
            LOAD_Q(ch + 1, (ch + 1) & 1);
            asm volatile("cp.async.wait_group 1;" ::: "memory");
        } else {
            asm volatile("cp.async.wait_group 0;" ::: "memory");
        }
        __syncthreads();
        uint32_t sA = sb + (ch & 1) * 32768;
        uint32_t sB = sA + 16384;
#pragma unroll
        for (int kk = 0; kk < 4; kk++) {
            uint32_t a[2][4];
#pragma unroll
            for (int mt = 0; mt < 2; mt++) {
                int r = wm*32 + mt*16 + (lane & 7) + ((lane >> 3) & 1) * 8;
                int cch = kk*2 + (lane >> 4);
                ldsm4(a[mt], sA + r*128 + ((cch ^ (r & 7)) << 4));
            }
            uint32_t b[8][2];
#pragma unroll
            for (int np = 0; np < 4; np++) {
                int r = wn*64 + np*16 + (lane & 7) + ((lane >> 4) & 1) * 8;
                int cch = kk*2 + ((lane >> 3) & 1);
                uint32_t d[4];
                ldsm4(d, sB + r*128 + ((cch ^ (r & 7)) << 4));
                b[2*np][0]=d[0]; b[2*np][1]=d[1];
                b[2*np+1][0]=d[2]; b[2*np+1][1]=d[3];
            }
#pragma unroll
            for (int mt = 0; mt < 2; mt++)
#pragma unroll
                for (int nt = 0; nt < 8; nt++)
                    mma_h(acc[mt][nt], a[mt], b[nt]);
        }
        __syncthreads();
    }

    int b_ = m0 >> 11;
    int ncol0 = n0 + wn*64;
    int h = ncol0 >> 6;
    float wv[8][2];
#pragma unroll
    for (int nt = 0; nt < 8; nt++) {
        int hd = nt*8 + (lane & 3)*2;
        wv[nt][0] = qnw[hd]; wv[nt][1] = qnw[hd + 1];
    }
#pragma unroll
    for (int mt = 0; mt < 2; mt++) {
#pragma unroll
        for (int half = 0; half < 2; half++) {
            int mrow = m0 + wm*32 + mt*16 + (lane >> 2) + half*8;
            int s = mrow & 2047;
            size_t rb = (((size_t)(b_*Hv + h))*Sv + s)*64;
            float ss = 0.f;
#pragma unroll
            for (int nt = 0; nt < 8; nt++) {
                float v0 = acc[mt][nt][half*2], v1 = acc[mt][nt][half*2+1];
                ss += v0*v0 + v1*v1;
            }
            ss += __shfl_xor_sync(0xffffffffu, ss, 1);
            ss += __shfl_xor_sync(0xffffffffu, ss, 2);
            float rinv = rsqrtf(ss / 64.f + 1e-6f);
#pragma unroll
            for (int nt = 0; nt < 8; nt++) {
                int hd = nt*8 + (lane & 3)*2;
                float v0 = acc[mt][nt][half*2]   * wv[nt][0] * rinv;
                float v1 = acc[mt][nt][half*2+1] * wv[nt][1] * rinv;
                *(float2*)&qout[rb + hd] = make_float2(v0, v1);
                *(__half2*)&qh[rb + hd] = __floats2half2_rn(v0, v1);
            }
        }
    }
#undef LOAD_Q
}

// ======== MLP GEMM 1: C[MT,256] = A[MT,64] @ B[256,64]^T ====================
// MODE 0: store fwd -> o1 = pre, o2 = gelu(pre).
// MODE 1: dh0       -> o1 = acc * gelu'(o2=pre0).
// MODE 2: retrieve  -> o1 = gelu single fp16.
template <int MODE>
__global__ void __launch_bounds__(256)
k_mlp0(const f16* __restrict__ A, const f16* __restrict__ Bw, long long ws,
       f16* __restrict__ o1, f16* __restrict__ o2) {
    extern __shared__ char sm[];
    uint32_t sb = smem_u32(sm);
    constexpr uint32_t SB = 8192u;
    int tid = threadIdx.x, wid = tid >> 5, lane = tid & 31;
    int wm = wid >> 2, wn = wid & 3;          // 2(M) x 4(N)
    int m0 = blockIdx.x * 64;
    int bh = m0 >> 11;

    {
        const f16* Ab = A + (size_t)m0 * 64;
#pragma unroll
        for (int i = 0; i < 2; i++) {
            int idx = i*256 + tid; int r = idx >> 3, g = idx & 7;
            cp16(sb + r*128 + ((g ^ (r & 7)) << 4), Ab + r*64 + g*8);
        }
        const f16* Bb = Bw + (size_t)bh * ws;
#pragma unroll
        for (int i = 0; i < 8; i++) {
            int idx = i*256 + tid; int r = idx >> 3, g = idx & 7;
            cp16(sb + SB + r*128 + ((g ^ (r & 7)) << 4), Bb + r*64 + g*8);
        }
    }
    asm volatile("cp.async.commit_group;\ncp.async.wait_group 0;" ::: "memory");
    __syncthreads();

    float acc[2][8][4];
#pragma unroll
    for (int mt = 0; mt < 2; mt++)
#pragma unroll
        for (int nt = 0; nt < 8; nt++)
#pragma unroll
            for (int e = 0; e < 4; e++) acc[mt][nt][e] = 0.f;

#pragma unroll
    for (int kk = 0; kk < 4; kk++) {
        uint32_t a[2][4];
#pragma unroll
        for (int mt = 0; mt < 2; mt++) {
            int r = wm*32 + mt*16 + (lane & 7) + ((lane >> 3) & 1) * 8;
            int cch = kk*2 + (lane >> 4);
            ldsm4(a[mt], sb + r*128 + ((cch ^ (r & 7)) << 4));
        }
        uint32_t b_r[8][2];
#pragma unroll
        for (int np = 0; np < 4; np++) {
            int r = wn*64 + np*16 + (lane & 7) + ((lane >> 4) & 1) * 8;
            int cch = kk*2 + ((lane >> 3) & 1);
            uint32_t d[4];
            ldsm4(d, sb + SB + r*128 + ((cch ^ (r & 7)) << 4));
            b_r[2*np][0]=d[0]; b_r[2*np][1]=d[1];
            b_r[2*np+1][0]=d[2]; b_r[2*np+1][1]=d[3];
        }
#pragma unroll
        for (int mt = 0; mt < 2; mt++)
#pragma unroll
            for (int nt = 0; nt < 8; nt++)
                mma_h(acc[mt][nt], a[mt], b_r[nt]);
    }

#pragma unroll
    for (int mt = 0; mt < 2; mt++) {
        int mrow = m0 + wm*32 + mt*16 + (lane >> 2);
#pragma unroll
        for (int nt = 0; nt < 8; nt++) {
            int c = wn*64 + nt*8 + (lane & 3) * 2;
#pragma unroll
            for (int half = 0; half < 2; half++) {
                size_t off = (size_t)(mrow + half*8) * 256 + c;
                float v0 = acc[mt][nt][half*2], v1 = acc[mt][nt][half*2 + 1];
                if (MODE == 0) {
                    *(__half2*)&o1[off] = __floats2half2_rn(v0, v1);
                    *(__half2*)&o2[off] = __floats2half2_rn(geluf(v0), geluf(v1));
                } else if (MODE == 1) {
                    __half2 p2 = *(const __half2*)&o2[off];
                    float2 pf = __half22float2(p2);
                    *(__half2*)&o1[off] =
                        __floats2half2_rn(v0 * gelugrad(pf.x), v1 * gelugrad(pf.y));
                } else {
                    *(__half2*)&o1[off] = __floats2half2_rn(geluf(v0), geluf(v1));
                }
            }
        }
    }
}

// ======== MLP GEMM 2 (store) + fused pf_rmsnorm bwd -> dhb =================
#define M1S_SMEM (32768 + 32768 + 2048)
__global__ void __launch_bounds__(256)
k_mlp1s(const f16* __restrict__ A, const f16* __restrict__ Bw,
        const f16* __restrict__ keysb, const f16* __restrict__ valh,
        f16* __restrict__ dhb) {
    extern __shared__ char sm[];
    uint32_t sb = smem_u32(sm);
    constexpr uint32_t SB = 32768u;
    float* RED1 = (float*)(sm + 65536);        // [128][2]
    float* RED2 = RED1 + 256;                  // [128][2]
    int tid = threadIdx.x, wid = tid >> 5, lane = tid & 31;
    int wm = wid >> 1, wn = wid & 1;
    int m0 = blockIdx.x * 128;

    {
#pragma unroll
        for (int i = 0; i < 8; i++) {
            int idx = i*256 + tid; int r = idx >> 5, g = idx & 31;
            cp16(sb + SB + r*512 + ((g ^ (r & 7)) << 4), Bw + r*256 + g*8);
        }
    }
#define LA1(CH, ST) do {                                                       \
    uint32_t _a = sb + (ST) * 16384u;                                          \
    _Pragma("unroll")                                                          \
    for (int i = 0; i < 4; i++) {                                              \
        int idx = i*256 + tid; int r = idx >> 3, g = idx & 7;                  \
        cp16(_a + r*128 + ((g ^ (r & 7)) << 4),                                \
             A + (size_t)(m0 + r)*256 + (CH)*64 + g*8);                        \
    }                                                                          \
    asm volatile("cp.async.commit_group;" ::: "memory");                       \
} while (0)

    LA1(0, 0);
    float acc[2][4][4];
#pragma unroll
    for (int mt = 0; mt < 2; mt++)
#pragma unroll
        for (int nt = 0; nt < 4; nt++)
#pragma unroll
            for (int e = 0; e < 4; e++) acc[mt][nt][e] = 0.f;

    for (int ch = 0; ch < 4; ch++) {
        if (ch < 3) {
            LA1(ch + 1, (ch + 1) & 1);
            asm volatile("cp.async.wait_group 1;" ::: "memory");
        } else {
            asm volatile("cp.async.wait_group 0;" ::: "memory");
        }
        __syncthreads();
        uint32_t sA = sb + (ch & 1) * 16384u;
#pragma unroll
        for (int kk = 0; kk < 4; kk++) {
            uint32_t a[2][4];
#pragma unroll
            for (int mt = 0; mt < 2; mt++) {
                int r = wm*32 + mt*16 + (lane & 7) + ((lane >> 3) & 1) * 8;
                int cch = kk*2 + (lane >> 4);
                ldsm4(a[mt], sA + r*128 + ((cch ^ (r & 7)) << 4));
            }
            uint32_t b_r[4][2];
#pragma unroll
            for (int np = 0; np < 2; np++) {
                int r = wn*32 + np*16 + (lane & 7) + ((lane >> 4) & 1) * 8;
                int kg = ch*8 + kk*2 + ((lane >> 3) & 1);
                uint32_t d[4];
                ldsm4(d, sb + SB + r*512 + ((kg ^ (r & 7)) << 4));
                b_r[2*np][0]=d[0]; b_r[2*np][1]=d[1];
                b_r[2*np+1][0]=d[2]; b_r[2*np+1][1]=d[3];
            }
#pragma unroll
            for (int mt = 0; mt < 2; mt++)
#pragma unroll
                for (int nt = 0; nt < 4; nt++)
                    mma_h(acc[mt][nt], a[mt], b_r[nt]);
        }
        __syncthreads();
    }

    // ---- fused pf_rmsnorm fwd+bwd epilogue ----
#pragma unroll
    for (int mt = 0; mt < 2; mt++)
#pragma unroll
        for (int half = 0; half < 2; half++) {
            float s = 0.f;
#pragma unroll
            for (int nt = 0; nt < 4; nt++) {
                float v0 = acc[mt][nt][half*2], v1 = acc[mt][nt][half*2+1];
                s += v0*v0 + v1*v1;
            }
            s += __shfl_xor_sync(0xffffffffu, s, 1);
            s += __shfl_xor_sync(0xffffffffu, s, 2);
            int rl = wm*32 + mt*16 + half*8 + (lane >> 2);
            if ((lane & 3) == 0) RED1[rl*2 + wn] = s;
        }
    __syncthreads();

    float rmsv[2][2], th[2][2];
    uint32_t k2[2][2][4], v2[2][2][4];
#pragma unroll
    for (int mt = 0; mt < 2; mt++)
#pragma unroll
        for (int half = 0; half < 2; half++) {
            int rl = wm*32 + mt*16 + half*8 + (lane >> 2);
            int mrow = m0 + rl;
            float tot = RED1[rl*2] + RED1[rl*2+1];
            float rms = sqrtf(tot / 64.f + 1e-8f);
            rmsv[mt][half] = rms;
            th[mt][half] = g_theta[mrow];
            float dy = 0.f;
#pragma unroll
            for (int nt = 0; nt < 4; nt++) {
                int c = wn*32 + nt*8 + (lane & 3)*2;
                size_t off = (size_t)mrow*64 + c;
                __half2 kk2 = *(const __half2*)&keysb[off];
                __half2 vv2 = *(const __half2*)&valh[off];
                k2[mt][half][nt] = *(uint32_t*)&kk2;
                v2[mt][half][nt] = *(uint32_t*)&vv2;
                float2 kf = __half22float2(kk2), vf = __half22float2(vv2);
                float hn0 = acc[mt][nt][half*2]   / rms;
                float hn1 = acc[mt][nt][half*2+1] / rms;
                float dp0 = 2.f * th[mt][half] * (hn0 + kf.x - vf.x);
                float dp1 = 2.f * th[mt][half] * (hn1 + kf.y - vf.y);
                dy += dp0*hn0 + dp1*hn1;
            }
            dy += __shfl_xor_sync(0xffffffffu, dy, 1);
            dy += __shfl_xor_sync(0xffffffffu, dy, 2);
            if ((lane & 3) == 0) RED2[rl*2 + wn] = dy;
        }
    __syncthreads();

#pragma unroll
    for (int mt = 0; mt < 2; mt++)
#pragma unroll
        for (int half = 0; half < 2; half++) {
            int rl = wm*32 + mt*16 + half*8 + (lane >> 2);
            int mrow = m0 + rl;
            float rms = rmsv[mt][half];
            float t = th[mt][half];
            float dy = (RED2[rl*2] + RED2[rl*2+1]) / 64.f;
#pragma unroll
            for (int nt = 0; nt < 4; nt++) {
                int c = wn*32 + nt*8 + (lane & 3)*2;
                uint32_t ku = k2[mt][half][nt], vu = v2[mt][half][nt];
                float2 kf = __half22float2(*(__half2*)&ku);
                float2 vf = __half22float2(*(__half2*)&vu);
                float hn0 = acc[mt][nt][half*2]   / rms;
                float hn1 = acc[mt][nt][half*2+1] / rms;
                float dp0 = 2.f * t * (hn0 + kf.x - vf.x);
                float dp1 = 2.f * t * (hn1 + kf.y - vf.y);
                float dh0 = (dp0 - hn0 * dy) / rms;
                float dh1 = (dp1 - hn1 * dy) / rms;
                *(__half2*)&dhb[(size_t)mrow*64 + c] = __floats2half2_rn(dh0, dh1);
            }
        }
#undef LA1
}

// ======== MLP GEMM 2 (retrieve) + fused nan_to_num/pf_rmsnorm/residual =====
#define M1R_SMEM (32768 + 32768 + 1024)
__global__ void __launch_bounds__(256)
k_mlp1r(const f16* __restrict__ A, const f16* __restrict__ Bw, long long ws,
        const float* __restrict__ qres, float* __restrict__ out) {
    extern __shared__ char sm[];
    uint32_t sb = smem_u32(sm);
    constexpr uint32_t SB = 32768u;
    float* RED1 = (float*)(sm + 65536);        // [128][2]
    int tid = threadIdx.x, wid = tid >> 5, lane = tid & 31;
    int wm = wid >> 1, wn = wid & 1;
    int m0 = blockIdx.x * 128;
    int bh = m0 >> 11;

    {
        const f16* Bb = Bw + (size_t)bh * ws;
#pragma unroll
        for (int i = 0; i < 8; i++) {
            int idx = i*256 + tid; int r = idx >> 5, g = idx & 31;
            cp16(sb + SB + r*512 + ((g ^ (r & 7)) << 4), Bb + r*256 + g*8);
        }
    }
#define LA2(CH, ST) do {                                                       \
    uint32_t _a = sb + (ST) * 16384u;                                          \
    _Pragma("unroll")                                                          \
    for (int i = 0; i < 4; i++) {                                              \
        int idx = i*256 + tid; int r = idx >> 3, g = idx & 7;                  \
        cp16(_a + r*128 + ((g ^ (r & 7)) << 4),                                \
             A + (size_t)(m0 + r)*256 + (CH)*64 + g*8);                        \
    }                                                                          \
    asm volatile("cp.async.commit_group;" ::: "memory");                       \
} while (0)

    LA2(0, 0);
    float acc[2][4][4];
#pragma unroll
    for (int mt = 0; mt < 2; mt++)
#pragma unroll
        for (int nt = 0; nt < 4; nt++)
#pragma unroll
            for (int e = 0; e < 4; e++) acc[mt][nt][e] = 0.f;

    for (int ch = 0; ch < 4; ch++) {
        if (ch < 3) {
            LA2(ch + 1, (ch + 1) & 1);
            asm volatile("cp.async.wait_group 1;" ::: "memory");
        } else {
            asm volatile("cp.async.wait_group 0;" ::: "memory");
        }
        __syncthreads();
        uint32_t sA = sb + (ch & 1) * 16384u;
#pragma unroll
        for (int kk = 0; kk < 4; kk++) {
            uint32_t a[2][4];
#pragma unroll
            for (int mt = 0; mt < 2; mt++) {
                int r = wm*32 + mt*16 + (lane & 7) + ((lane >> 3) & 1) * 8;
                int cch = kk*2 + (lane >> 4);
                ldsm4(a[mt], sA + r*128 + ((cch ^ (r & 7)) << 4));
            }
            uint32_t b_r[4][2];
#pragma unroll
            for (int np = 0; np < 2; np++) {
                int r = wn*32 + np*16 + (lane & 7) + ((lane >> 4) & 1) * 8;
                int kg = ch*8 + kk*2 + ((lane >> 3) & 1);
                uint32_t d[4];
                ldsm4(d, sb + SB + r*512 + ((kg ^ (r & 7)) << 4));
                b_r[2*np][0]=d[0]; b_r[2*np][1]=d[1];
                b_r[2*np+1][0]=d[2]; b_r[2*np+1][1]=d[3];
            }
#pragma unroll
            for (int mt = 0; mt < 2; mt++)
#pragma unroll
                for (int nt = 0; nt < 4; nt++)
                    mma_h(acc[mt][nt], a[mt], b_r[nt]);
        }
        __syncthreads();
    }

    // ---- fused nan_to_num + pf_rmsnorm + residual + split-head store ----
#pragma unroll
    for (int mt = 0; mt < 2; mt++)
#pragma unroll
        for (int nt = 0; nt < 4; nt++)
#pragma unroll
            for (int e = 0; e < 4; e++)
                if (!isfinite(acc[mt][nt][e])) acc[mt][nt][e] = 0.f;

#pragma unroll
    for (int mt = 0; mt < 2; mt++)
#pragma unroll
        for (int half = 0; half < 2; half++) {
            float s = 0.f;
#pragma unroll
            for (int nt = 0; nt < 4; nt++) {
                float v0 = acc[mt][nt][half*2], v1 = acc[mt][nt][half*2+1];
                s += v0*v0 + v1*v1;
            }
            s += __shfl_xor_sync(0xffffffffu, s, 1);
            s += __shfl_xor_sync(0xffffffffu, s, 2);
            int rl = wm*32 + mt*16 + half*8 + (lane >> 2);
            if ((lane & 3) == 0) RED1[rl*2 + wn] = s;
        }
    __syncthreads();

    int bb = bh >> 4, hh = bh & 15;
#pragma unroll
    for (int mt = 0; mt < 2; mt++)
#pragma unroll
        for (int half = 0; half < 2; half++) {
            int rl = wm*32 + mt*16 + half*8 + (lane >> 2);
            int mrow = m0 + rl;
            int s = mrow & 2047;
            float rms = sqrtf((RED1[rl*2] + RED1[rl*2+1]) / 64.f + 1e-8f);
            size_t ob = ((size_t)(bb*Sv + s))*Dv + hh*64;
#pragma unroll
            for (int nt = 0; nt < 4; nt++) {
                int c = wn*32 + nt*8 + (lane & 3)*2;
                float2 qv = *(const float2*)&qres[(size_t)mrow*64 + c];
                float o0 = acc[mt][nt][half*2]   / rms + qv.x;
                float o1 = acc[mt][nt][half*2+1] / rms + qv.y;
                *(float2*)&out[ob + c] = make_float2(o0, o1);
            }
        }
#undef LA2
}

// ======== gradT ============================================================
template <int MI, int NO>
__global__ void __launch_bounds__(256)
k_gradmma(const f16* __restrict__ A, const f16* __restrict__ Bm,
          float* __restrict__ G) {
    __shared__ __align__(16) char sm[32768];
    uint32_t sb = smem_u32(sm);
    int tid = threadIdx.x, wid = tid >> 5, lane = tid & 31;
    int wm = wid >> 2, wn = wid & 3;
    int bh = blockIdx.z;
    int m0 = blockIdx.y * 64, n0 = blockIdx.x * 64;
    const f16* Ab = A  + ((size_t)bh * Sv) * MI + m0;
    const f16* Bb = Bm + ((size_t)bh * Sv) * NO + n0;

#define LG(ST, S0) do {                                                        \
    _Pragma("unroll")                                                          \
    for (int i = 0; i < 2; i++) {                                              \
        int idx = i*256 + tid; int r = idx >> 3, g = idx & 7;                  \
        cp16(sb + (ST)*8192 + r*128 + ((g ^ (r & 7)) << 4),                    \
             Ab + (size_t)((S0) + r)*MI + g*8);                                \
        cp16(sb + 16384 + (ST)*8192 + r*128 + ((g ^ (r & 7)) << 4),            \
             Bb + (size_t)((S0) + r)*NO + g*8);                                \
    }                                                                          \
    asm volatile("cp.async.commit_group;" ::: "memory");                       \
} while (0)

    LG(0, 0);
    float acc[2][2][4];
#pragma unroll
    for (int mt = 0; mt < 2; mt++)
#pragma unroll
        for (int nt = 0; nt < 2; nt++)
#pragma unroll
            for (int e = 0; e < 4; e++) acc[mt][nt][e] = 0.f;

    for (int st = 0; st < 32; st++) {
        if (st < 31) {
            LG((st + 1) & 1, (st + 1) * 64);
            asm volatile("cp.async.wait_group 1;" ::: "memory");
        } else {
            asm volatile("cp.async.wait_group 0;" ::: "memory");
        }
        __syncthreads();
        uint32_t sA = sb + (st & 1) * 8192;
        uint32_t sB = sb + 16384 + (st & 1) * 8192;
#pragma unroll
        for (int kk = 0; kk < 4; kk++) {
            uint32_t aT[2][4];
#pragma unroll
            for (int mt = 0; mt < 2; mt++) {
                int row = kk*16 + (lane & 7) + ((lane >> 4) & 1) * 8;
                int cg = wm*4 + mt*2 + ((lane >> 3) & 1);
                ldsm4t(aT[mt], sA + row*128 + ((cg ^ (row & 7)) << 4));
            }
            int row = kk*16 + (lane & 7) + ((lane >> 3) & 1) * 8;
            int cg = wn*2 + (lane >> 4);
            uint32_t d[4];
            ldsm4t(d, sB + row*128 + ((cg ^ (row & 7)) << 4));
            uint32_t bT[2][2] = {{d[0], d[1]}, {d[2], d[3]}};
#pragma unroll
            for (int mt = 0; mt < 2; mt++)
#pragma unroll
                for (int nt = 0; nt < 2; nt++)
                    mma_h(acc[mt][nt], aT[mt], bT[nt]);
        }
        __syncthreads();
    }
#pragma unroll
    for (int mt = 0; mt < 2; mt++) {
        int m = m0 + wm*32 + mt*16 + (lane >> 2);
#pragma unroll
        for (int nt = 0; nt < 2; nt++) {
            int n = n0 + wn*16 + nt*8 + (lane & 3) * 2;
            *(float2*)&G[((size_t)bh*MI + m)*NO + n]     = make_float2(acc[mt][nt][0], acc[mt][nt][1]);
            *(float2*)&G[((size_t)bh*MI + m + 8)*NO + n] = make_float2(acc[mt][nt][2], acc[mt][nt][3]);
        }
    }
#undef LG
}

// ---------------- gates: alpha, theta (reads fp16 xn) -----------------------
__global__ void __launch_bounds__(256)
k_gates(const f16* __restrict__ xn,
        const float* __restrict__ aw, const float* __restrict__ ab,
        const float* __restrict__ tw, const float* __restrict__ tb) {
    __shared__ float Xs[64][128];
    __shared__ float Ws[64][32];
    int m0 = blockIdx.x * 128;
    int tid = threadIdx.x;
    int rg = tid >> 3, cg = tid & 7;
    float acc[4][4] = {};
    for (int k0 = 0; k0 < 1024; k0 += 64) {
#pragma unroll
        for (int i = 0; i < 4; i++) {
            int idx = tid + i*256;
            int r = idx >> 3, c8 = idx & 7;
            size_t ga = (size_t)(m0 + r)*1024 + k0 + c8*8;
            uint4 vh = *(const uint4*)&xn[ga];
            __half2 h2[4];
            *(uint4*)h2 = vh;
#pragma unroll
            for (int j = 0; j < 4; j++) {
                float2 fh = __half22float2(h2[j]);
                Xs[c8*8 + 2*j][r]     = fh.x;
                Xs[c8*8 + 2*j + 1][r] = fh.y;
            }
        }
#pragma unroll
        for (int i = 0; i < 2; i++) {
            int idx = tid + i*256;
            int r = idx >> 3, c4 = idx & 7;
            const float* src = (c4 < 4) ? (aw + (size_t)(k0 + r)*16 + c4*4)
                                        : (tw + (size_t)(k0 + r)*16 + (c4 - 4)*4);
            *(float4*)&Ws[r][c4*4] = *(const float4*)src;
        }
        __syncthreads();
#pragma unroll
        for (int k = 0; k < 64; k++) {
            float ra[4], rb[4];
#pragma unroll
            for (int i = 0; i < 4; i++) ra[i] = Xs[k][rg*4 + i];
#pragma unroll
            for (int j = 0; j < 4; j++) rb[j] = Ws[k][cg*4 + j];
#pragma unroll
            for (int i = 0; i < 4; i++)
#pragma unroll
                for (int j = 0; j < 4; j++) acc[i][j] += ra[i] * rb[j];
        }
        __syncthreads();
    }
#pragma unroll
    for (int i = 0; i < 4; i++) {
        int m = m0 + rg*4 + i;
        int b = m >> 11, s = m & 2047;
#pragma unroll
        for (int j = 0; j < 4; j++) {
            int c = cg*4 + j;
            int h = c & 15;
            size_t off = ((size_t)(b*Hv + h))*Sv + s;
            if (c < 16) g_alpha[off] = 1.f / (1.f + expf(-(acc[i][j] + ab[h])));
            else        g_theta[off] = 0.01f / (1.f + expf(-(acc[i][j] + tb[h])));
        }
    }
}

// ---------------- per-bh reductions -----------------------------------------
__global__ void k_amean() {
    int bh = blockIdx.x; int tid = threadIdx.x;
    float s = 0.f;
    for (int i = tid; i < Sv; i += 256) s += g_alpha[(size_t)bh*Sv + i];
#pragma unroll
    for (int o = 16; o > 0; o >>= 1) s += __shfl_xor_sync(0xffffffffu, s, o);
    __shared__ float red[8];
    if ((tid & 31) == 0) red[tid >> 5] = s;
    __syncthreads();
    if (tid == 0) {
        float t = 0.f;
#pragma unroll
        for (int i = 0; i < 8; i++) t += red[i];
        g_amean[bh] = t / (float)Sv;
    }
}

__global__ void k_clip() {
    int bh = blockIdx.x; int tid = threadIdx.x;
    const float* a = g_g0 + (size_t)bh * 16384;
    const float* b = g_g1 + (size_t)bh * 16384;
    float s = 0.f;
    for (int i = tid; i < 16384; i += 256) {
        float v = a[i]; s += v*v;
        v = b[i]; s += v*v;
    }
#pragma unroll
    for (int o = 16; o > 0; o >>= 1) s += __shfl_xor_sync(0xffffffffu, s, o);
    __shared__ float red[8];
    if ((tid & 31) == 0) red[tid >> 5] = s;
    __syncthreads();
    if (tid == 0) {
        float t = 0.f;
#pragma unroll
        for (int i = 0; i < 8; i++) t += red[i];
        float c = 10.f / (sqrtf(t) + 1e-6f);
        g_coef[bh] = c < 1.f ? c : 1.f;
    }
}

// ---------------- weight prep + update --------------------------------------
__global__ void k_tr(const float* __restrict__ src, float* __restrict__ dstF,
                     f16* __restrict__ dstB, int R, int C) {
    int idx = blockIdx.x * 256 + threadIdx.x;
    if (idx >= R*C) return;
    int c = idx / R, r = idx % R;
    float v = src[r*C + c];
    dstF[idx] = v;
    dstB[idx] = __float2half(v);
}
__global__ void k_cpb(const float* __restrict__ s, f16* __restrict__ d, int n) {
    int idx = blockIdx.x * 256 + threadIdx.x;
    if (idx < n) d[idx] = __float2half(s[idx]);
}
__global__ void k_newwT(const float* __restrict__ WT, const float* __restrict__ gT,
                        f16* __restrict__ o) {
    size_t idx = (size_t)blockIdx.x * 256 + threadIdx.x;
    int bh = (int)(idx >> 14); int e = (int)(idx & 16383);
    float w = WT[e];
    float nw = (1.f - g_amean[bh]) * w - g_coef[bh] * gT[idx];
    if (!isfinite(nw)) nw = w;
    o[idx] = __float2half(nw);
}

// ============================================================================
extern "C" void kernel_launch(void* const* d_in, const int* in_sizes, int n_in,
                              void* d_out, int out_size) {
    (void)in_sizes; (void)n_in; (void)out_size;
    const float* x   = (const float*)d_in[0];
    const float* W_K = (const float*)d_in[1];
    const float* W_V = (const float*)d_in[2];
    const float* W_Q = (const float*)d_in[3];
    const float* mW0 = (const float*)d_in[4];
    const float* mW1 = (const float*)d_in[5];
    const float* knw = (const float*)d_in[6];
    const float* qnw = (const float*)d_in[7];
    const float* snw = (const float*)d_in[8];
    const float* rnw = (const float*)d_in[9];
    const float* aw  = (const float*)d_in[10];
    const float* ab  = (const float*)d_in[11];
    const float* tw  = (const float*)d_in[12];
    const float* tb  = (const float*)d_in[13];
    float* out = (float*)d_out;

    f16 *xnh, *wkv, *wq, *keysb, *qh, *dhb, *valh;
    f16 *mW0Tb, *mW1Tb, *mW1b, *nW0T, *nW1T;
    float *q, *g0p, *g1p, *mW0T, *mW1T;
    char* pool;
    cudaGetSymbolAddress((void**)&xnh,    g_xnh);
    cudaGetSymbolAddress((void**)&wkv,    g_wkv);
    cudaGetSymbolAddress((void**)&wq,     g_wq);
    cudaGetSymbolAddress((void**)&valh,   g_values);
    cudaGetSymbolAddress((void**)&q,      g_q);
    cudaGetSymbolAddress((void**)&keysb,  g_keysb);
    cudaGetSymbolAddress((void**)&qh,     g_qh);
    cudaGetSymbolAddress((void**)&dhb,    g_dhb);
    cudaGetSymbolAddress((void**)&pool,   g_pool);
    cudaGetSymbolAddress((void**)&g0p,    g_g0);
    cudaGetSymbolAddress((void**)&g1p,    g_g1);
    cudaGetSymbolAddress((void**)&mW0T,   g_mW0T);
    cudaGetSymbolAddress((void**)&mW1T,   g_mW1T);
    cudaGetSymbolAddress((void**)&mW0Tb,  g_mW0Tb);
    cudaGetSymbolAddress((void**)&mW1Tb,  g_mW1Tb);
    cudaGetSymbolAddress((void**)&mW1b,   g_mW1b);
    cudaGetSymbolAddress((void**)&nW0T,   g_nW0T);
    cudaGetSymbolAddress((void**)&nW1T,   g_nW1T);

    f16* pre0h = (f16*)(pool);
    f16* h1h   = (f16*)(pool + 134217728);
    f16* dh0h  = (f16*)(pool + 268435456);
    f16* h1rh  = (f16*)(pool);                // aliases pre0h (dead by then)

    cudaFuncSetAttribute(k_gemm_kv, cudaFuncAttributeMaxDynamicSharedMemorySize, KV_SMEM);
    cudaFuncSetAttribute(k_gemm_q,  cudaFuncAttributeMaxDynamicSharedMemorySize, KV_SMEM);
    cudaFuncSetAttribute(k_mlp0<0>, cudaFuncAttributeMaxDynamicSharedMemorySize, 40960);
    cudaFuncSetAttribute(k_mlp0<1>, cudaFuncAttributeMaxDynamicSharedMemorySize, 40960);
    cudaFuncSetAttribute(k_mlp0<2>, cudaFuncAttributeMaxDynamicSharedMemorySize, 40960);
    cudaFuncSetAttribute(k_mlp1s,   cudaFuncAttributeMaxDynamicSharedMemorySize, M1S_SMEM);
    cudaFuncSetAttribute(k_mlp1r,   cudaFuncAttributeMaxDynamicSharedMemorySize, M1R_SMEM);

    dim3 gws(32, 32), bws(32, 8);

    // ---- weight prep (independent) ----
    k_tr<<<64, 256>>>(mW0, mW0T, mW0Tb, HDv, HIDv);   // -> [256][64]
    k_tr<<<64, 256>>>(mW1, mW1T, mW1Tb, HIDv, HDv);   // -> [64][256]
    k_cpb<<<64, 256>>>(mW1, mW1b, HIDv*HDv);

    // ---- store path ----
    k_rmsnorm16<<<Mv, 256>>>(x, snw, xnh);
    k_wt16<<<gws, bws>>>(W_K, wkv);
    k_wt16<<<gws, bws>>>(W_V, wkv + (size_t)Dv*Dv);
    k_gemm_kv<<<dim3(16, 128), 256, KV_SMEM>>>(xnh, wkv, keysb, valh, knw);
    k_gates<<<Mv/128, 256>>>(xnh, aw, ab, tw, tb);
    k_amean<<<BHv, 256>>>();

    k_mlp0<0><<<MTv/64, 256, 40960>>>(keysb, mW0Tb, 0, pre0h, h1h);
    k_mlp1s<<<MTv/128, 256, M1S_SMEM>>>(h1h, mW1Tb, keysb, valh, dhb);
    // dh0 written in place over pre0h (same-thread same-offset read/write)
    k_mlp0<1><<<MTv/64, 256, 40960>>>(dhb, mW1b, 0, dh0h, pre0h);

    k_gradmma<HDv, HIDv><<<dim3(4, 1, BHv), 256>>>(dhb, h1h, g1p);     // g1^T [64][256]
    k_gradmma<HIDv, HDv><<<dim3(1, 4, BHv), 256>>>(dh0h, keysb, g0p);  // g0^T [256][64]
    k_clip<<<BHv, 256>>>();
    k_newwT<<<(BHv*16384)/256, 256>>>(mW0T, g0p, nW0T);
    k_newwT<<<(BHv*16384)/256, 256>>>(mW1T, g1p, nW1T);

    // ---- retrieve path ----
    k_rmsnorm16<<<Mv, 256>>>(x, rnw, xnh);
    k_wt16<<<gws, bws>>>(W_Q, wq);
    k_gemm_q<<<dim3(8, 128), 256, KV_SMEM>>>(xnh, wq, q, qh, qnw);
    k_mlp0<2><<<MTv/64, 256, 40960>>>(qh, nW0T, (long long)HIDv*HDv, h1rh, nullptr);
    k_mlp1r<<<MTv/128, 256, M1R_SMEM>>>(h1rh, nW1T, (long long)HDv*HIDv, q, out);
}